// round 11
// baseline (speedup 1.0000x reference)
#include <cuda_runtime.h>
#include <cuda_bf16.h>
#include <math.h>
#include <float.h>
#include <stdint.h>

#define NMAX 50000
#define BMAX 1024

__device__ float g_wall_h[BMAX * 64];
__device__ float g_h[NMAX * 128];
__device__ float g_hcn[NMAX * 256];
__device__ float g_sinv[NMAX];
__device__ __align__(16) __nv_bfloat16 g_x1h[NMAX * 320];
__device__ __align__(16) __nv_bfloat16 g_x1l[NMAX * 320];
__device__ __align__(16) __nv_bfloat16 g_x2h[NMAX * 320];
__device__ __align__(16) __nv_bfloat16 g_x2l[NMAX * 320];
__device__ __align__(16) __nv_bfloat16 g_Wt1h[256 * 320];
__device__ __align__(16) __nv_bfloat16 g_Wt1l[256 * 320];
__device__ __align__(16) __nv_bfloat16 g_Wt2h[256 * 320];
__device__ __align__(16) __nv_bfloat16 g_Wt2l[256 * 320];
__device__ __align__(16) __nv_bfloat16 g_W2th[128 * 128];
__device__ __align__(16) __nv_bfloat16 g_W2tl[128 * 128];
__device__ float g_bc1[256];
__device__ float g_bc2[256];

// ---- helpers ----
__device__ __forceinline__ uint32_t smem_u32(const void* p) {
    uint32_t a;
    asm("{ .reg .u64 t; cvta.to.shared.u64 t, %1; cvt.u32.u64 %0, t; }" : "=r"(a) : "l"(p));
    return a;
}
__device__ __forceinline__ void ldsm_x4(uint32_t* r, uint32_t addr) {
    asm volatile("ldmatrix.sync.aligned.m8n8.x4.shared.b16 {%0,%1,%2,%3}, [%4];"
                 : "=r"(r[0]), "=r"(r[1]), "=r"(r[2]), "=r"(r[3]) : "r"(addr));
}
__device__ __forceinline__ void mma_bf16(float* c, const uint32_t* a, const uint32_t* b) {
    asm volatile("mma.sync.aligned.m16n8k16.row.col.f32.bf16.bf16.f32 "
                 "{%0,%1,%2,%3}, {%4,%5,%6,%7}, {%8,%9}, {%0,%1,%2,%3};"
                 : "+f"(c[0]), "+f"(c[1]), "+f"(c[2]), "+f"(c[3])
                 : "r"(a[0]), "r"(a[1]), "r"(a[2]), "r"(a[3]), "r"(b[0]), "r"(b[1]));
}
#define CP_ASYNC(dst, src) \
    asm volatile("cp.async.cg.shared.global [%0], [%1], 16;" :: "r"(dst), "l"(src) : "memory")
#define CP_COMMIT() asm volatile("cp.async.commit_group;" ::: "memory")
#define CP_WAIT(n)  asm volatile("cp.async.wait_group %0;" :: "n"(n) : "memory")

__device__ __forceinline__ uint32_t pack_hi(float a, float b, float& ra, float& rb) {
    __nv_bfloat16 ha = __float2bfloat16(a), hb = __float2bfloat16(b);
    ra = a - __bfloat162float(ha); rb = b - __bfloat162float(hb);
    __nv_bfloat162 p(ha, hb);
    return *reinterpret_cast<uint32_t*>(&p);
}
__device__ __forceinline__ uint32_t pack_lo(float a, float b) {
    __nv_bfloat162 p(__float2bfloat16(a), __float2bfloat16(b));
    return *reinterpret_cast<uint32_t*>(&p);
}
__device__ __forceinline__ unsigned long long dup2(float x) {
    unsigned long long r; asm("mov.b64 %0, {%1, %1};" : "=l"(r) : "f"(x)); return r;
}
__device__ __forceinline__ void ffma2(unsigned long long& d, unsigned long long a, unsigned long long b) {
    asm("fma.rn.f32x2 %0, %1, %2, %0;" : "+l"(d) : "l"(a), "l"(b));
}
__device__ __forceinline__ float2 unpack2(unsigned long long p) {
    float lo, hi; asm("mov.b64 {%0, %1}, %2;" : "=f"(lo), "=f"(hi) : "l"(p)); return make_float2(lo, hi);
}

// ---------------------------------------------------------------------------
__global__ void __launch_bounds__(256) setup_weights(
    const float* __restrict__ m1W1, const float* __restrict__ m1b1,
    const float* __restrict__ m2W1, const float* __restrict__ m2b1,
    const float* __restrict__ m1W2) {
    int b = blockIdx.x, tid = threadIdx.x;
    if (b < 640) {
        int sel = b >= 320;
        const float* W1 = sel ? m2W1 : m1W1;
        const float* b1 = sel ? m2b1 : m1b1;
        __nv_bfloat16* Wh = sel ? g_Wt2h : g_Wt1h;
        __nv_bfloat16* Wl = sel ? g_Wt2l : g_Wt1l;
        float* bc = sel ? g_bc2 : g_bc1;
        int idx = (sel ? b - 320 : b) * 256 + tid;
        if (idx < 256 * 320) {
            int c = idx / 320, k = idx - c * 320;
            float v = (c < 128) ? (W1[k*128+c] - W1[(k+320)*128+c]) : W1[(k+320)*128+(c-128)];
            __nv_bfloat16 h = __float2bfloat16(v);
            Wh[idx] = h; Wl[idx] = __float2bfloat16(v - __bfloat162float(h));
        }
        if (idx < 256) bc[idx] = (idx < 128) ? b1[idx] : 0.f;
    } else {
        int idx = (b - 640) * 256 + tid;
        int c = idx >> 7, k = idx & 127;
        float v = m1W2[k*128+c];
        __nv_bfloat16 h = __float2bfloat16(v);
        g_W2th[idx] = h; g_W2tl[idx] = __float2bfloat16(v - __bfloat162float(h));
    }
}

__global__ void __launch_bounds__(256) setup_wall(
    const float* __restrict__ wall, const float* __restrict__ w1,
    const float* __restrict__ wb1, const float* __restrict__ w2,
    const float* __restrict__ wb2, int B) {
    __shared__ float h[4][64];
    int tid = threadIdx.x;
    int row = blockIdx.x * 4 + (tid >> 6), k = tid & 63, rr = tid >> 6;
    if (row < B)
        h[rr][k] = fmaxf(wall[row*2]*w1[k] + wall[row*2+1]*w1[64+k] + wb1[k], 0.f);
    __syncthreads();
    if (row < B) {
        float acc = wb2[k];
#pragma unroll 8
        for (int i = 0; i < 64; i++) acc += h[rr][i] * w2[i*64+k];
        g_wall_h[row*64+k] = fmaxf(acc, 0.f);
    }
}

// ---------------------------------------------------------------------------
__global__ void __launch_bounds__(256) node_kernel(
    const float* __restrict__ t, const float* __restrict__ obj_x, const float* __restrict__ obj_geo,
    const int* __restrict__ category, const int* __restrict__ batch_idx,
    const float* __restrict__ embed_W, const float* __restrict__ gfp_W,
    const float* __restrict__ sW, const float* __restrict__ sb,
    const float* __restrict__ i1, const float* __restrict__ ib1, int N) {
    __shared__ float sWsh[64*64], i1sh[6*128], embsh[10*64], gfpsh[32], ib1sh[128], sbsh[64];
    __shared__ float2 gd[8][64];
    int tid = threadIdx.x, warp = tid >> 5, lane = tid & 31;
    for (int i = tid; i < 4096; i += 256) sWsh[i] = sW[i];
    for (int i = tid; i < 768; i += 256) i1sh[i] = i1[i];
    for (int i = tid; i < 640; i += 256) embsh[i] = embed_W[i];
    if (tid < 32) gfpsh[tid] = gfp_W[tid];
    if (tid < 128) ib1sh[tid] = ib1[tid];
    if (tid < 64) sbsh[tid] = sb[tid];
    __syncthreads();
    int base = blockIdx.x * 32;
#pragma unroll
    for (int it = 0; it < 4; it++) {
        int n = base + it * 8 + warp;
        if (n >= N) continue;
        float tv = __ldg(t + n);
        float p = tv * gfpsh[lane] * 6.283185307179586f;
        float sv = sinf(p), cv = cosf(p);
        gd[warp][lane] = make_float2(sv, sv);
        gd[warp][lane+32] = make_float2(cv, cv);
        int cat = category[n], bi = batch_idx[n];
        uint32_t* x1hu = reinterpret_cast<uint32_t*>(g_x1h);
        uint32_t* x1lu = reinterpret_cast<uint32_t*>(g_x1l);
        size_t nb = (size_t)n * 160;
        {
            float v0 = fmaxf(embsh[cat*64 + 2*lane], 0.f);
            float v1 = fmaxf(embsh[cat*64 + 2*lane + 1], 0.f);
            float r0, r1;
            x1hu[nb + 64 + lane] = pack_hi(v0, v1, r0, r1);
            x1lu[nb + 64 + lane] = pack_lo(r0, r1);
        }
        {
            float v0 = g_wall_h[bi*64 + 2*lane], v1 = g_wall_h[bi*64 + 2*lane + 1];
            float r0, r1;
            x1hu[nb + 128 + lane] = pack_hi(v0, v1, r0, r1);
            x1lu[nb + 128 + lane] = pack_lo(r0, r1);
        }
        if (lane == 0) {
            const float LN25 = 3.2188758248682006f;
            float stdv = sqrtf((expf(2.f*tv*LN25) - 1.f) / (2.f*LN25));
            g_sinv[n] = 1.f / (stdv + 1e-7f);
        }
        float xv = 0.f;
        if (lane < 4) xv = obj_x[n*4+lane]; else if (lane < 6) xv = obj_geo[n*2+lane-4];
        float4 a = *reinterpret_cast<const float4*>(ib1sh + lane*4);
#pragma unroll
        for (int i = 0; i < 6; i++) {
            float xi = __shfl_sync(0xffffffffu, xv, i);
            float4 w = *reinterpret_cast<const float4*>(i1sh + i*128 + lane*4);
            a.x += xi*w.x; a.y += xi*w.y; a.z += xi*w.z; a.w += xi*w.w;
        }
        a.x = fmaxf(a.x,0.f); a.y = fmaxf(a.y,0.f); a.z = fmaxf(a.z,0.f); a.w = fmaxf(a.w,0.f);
        *reinterpret_cast<float4*>(g_h + (size_t)n*128 + lane*4) = a;
        __syncwarp();
        unsigned long long accp = *reinterpret_cast<const unsigned long long*>(sbsh + lane*2);
#pragma unroll 8
        for (int i = 0; i < 64; i++)
            ffma2(accp, *reinterpret_cast<const unsigned long long*>(&gd[warp][i]),
                  *reinterpret_cast<const unsigned long long*>(sWsh + i*64 + lane*2));
        float2 v = unpack2(accp);
        v.x = fmaxf(v.x,0.f); v.y = fmaxf(v.y,0.f);
        float r0, r1;
        x1hu[nb + 96 + lane] = pack_hi(v.x, v.y, r0, r1);
        x1lu[nb + 96 + lane] = pack_lo(r0, r1);
        __syncwarp();
    }
}

// ---------------------------------------------------------------------------
__global__ void __launch_bounds__(256, 2) gemm128(
    const float* __restrict__ A, const float* __restrict__ W,
    const float* __restrict__ bias, int N) {
    __shared__ float At[16][132], Ws[16][128];
    int tid = threadIdx.x, rowBase = blockIdx.x * 128;
    int rg = tid >> 4, cg = tid & 15;
    unsigned long long acc[8][4];
#pragma unroll
    for (int r = 0; r < 8; r++) for (int c = 0; c < 4; c++) acc[r][c] = 0ULL;
    for (int kc = 0; kc < 128; kc += 16) {
        __syncthreads();
#pragma unroll
        for (int i = 0; i < 2; i++) {
            int idx = tid + i*256, r = idx >> 2, kq = (idx & 3) << 2;
            int row = rowBase + r; if (row > N-1) row = N-1;
            float4 v = *reinterpret_cast<const float4*>(A + (size_t)row*128 + kc + kq);
            At[kq][r] = v.x; At[kq+1][r] = v.y; At[kq+2][r] = v.z; At[kq+3][r] = v.w;
        }
#pragma unroll
        for (int i = 0; i < 2; i++) {
            int idx = tid + i*256, k = idx >> 5, c4 = (idx & 31) << 2;
            *reinterpret_cast<float4*>(&Ws[k][c4]) =
                *reinterpret_cast<const float4*>(W + (size_t)(kc+k)*128 + c4);
        }
        __syncthreads();
#pragma unroll
        for (int kk = 0; kk < 16; kk++) {
            float4 a0 = *reinterpret_cast<const float4*>(&At[kk][rg*8]);
            float4 a1 = *reinterpret_cast<const float4*>(&At[kk][rg*8+4]);
            ulonglong2 w0 = *reinterpret_cast<const ulonglong2*>(&Ws[kk][cg*8]);
            ulonglong2 w1 = *reinterpret_cast<const ulonglong2*>(&Ws[kk][cg*8+4]);
            unsigned long long ad[8] = {dup2(a0.x),dup2(a0.y),dup2(a0.z),dup2(a0.w),
                                        dup2(a1.x),dup2(a1.y),dup2(a1.z),dup2(a1.w)};
#pragma unroll
            for (int r = 0; r < 8; r++) {
                ffma2(acc[r][0], ad[r], w0.x); ffma2(acc[r][1], ad[r], w0.y);
                ffma2(acc[r][2], ad[r], w1.x); ffma2(acc[r][3], ad[r], w1.y);
            }
        }
    }
    float4 b0 = *reinterpret_cast<const float4*>(bias + cg*8);
    float4 b1 = *reinterpret_cast<const float4*>(bias + cg*8 + 4);
    uint32_t* x1hu = reinterpret_cast<uint32_t*>(g_x1h);
    uint32_t* x1lu = reinterpret_cast<uint32_t*>(g_x1l);
#pragma unroll
    for (int r = 0; r < 8; r++) {
        int row = rowBase + rg*8 + r;
        if (row < N) {
            float2 v0 = unpack2(acc[r][0]), v1 = unpack2(acc[r][1]);
            float2 v2 = unpack2(acc[r][2]), v3 = unpack2(acc[r][3]);
            float o[8] = {fmaxf(v0.x+b0.x,0.f), fmaxf(v0.y+b0.y,0.f),
                          fmaxf(v1.x+b0.z,0.f), fmaxf(v1.y+b0.w,0.f),
                          fmaxf(v2.x+b1.x,0.f), fmaxf(v2.y+b1.y,0.f),
                          fmaxf(v3.x+b1.z,0.f), fmaxf(v3.y+b1.w,0.f)};
            uint32_t hh[4], ll[4];
#pragma unroll
            for (int q = 0; q < 4; q++) {
                float r0, r1;
                hh[q] = pack_hi(o[q*2], o[q*2+1], r0, r1);
                ll[q] = pack_lo(r0, r1);
            }
            size_t u = (size_t)row * 160 + cg * 4;
            *reinterpret_cast<uint2*>(x1hu + u)     = make_uint2(hh[0], hh[1]);
            *reinterpret_cast<uint2*>(x1hu + u + 2) = make_uint2(hh[2], hh[3]);
            *reinterpret_cast<uint2*>(x1lu + u)     = make_uint2(ll[0], ll[1]);
            *reinterpret_cast<uint2*>(x1lu + u + 2) = make_uint2(ll[2], ll[3]);
        }
    }
}

// ---------------------------------------------------------------------------
// mma.sync GEMM, cp.async double buffered (unchanged; at HMMA rt floor).
// ---------------------------------------------------------------------------
#define MG_SMEM 81920
__global__ void __launch_bounds__(256, 2) mma_gemm(
    const __nv_bfloat16* __restrict__ Ah, const __nv_bfloat16* __restrict__ Al,
    const __nv_bfloat16* __restrict__ Bh, const __nv_bfloat16* __restrict__ Bl,
    const float* __restrict__ bias, float* __restrict__ out, int N) {
    extern __shared__ char sm[];
    uint32_t smb = smem_u32(sm);
    int tid = threadIdx.x, lane = tid & 31, warp = tid >> 5;
    int wm = warp & 3, wn = warp >> 2;
    int rowBase = blockIdx.x * 128, colBase = blockIdx.y * 128;
    float acc[2][8][4];
#pragma unroll
    for (int m = 0; m < 2; m++) for (int n = 0; n < 8; n++)
        for (int q = 0; q < 4; q++) acc[m][n][q] = 0.f;
    int aRow = lane & 15, aK = (lane >> 4) * 8;
    int bN = ((lane >> 4) << 3) + (lane & 7), bK = ((lane >> 3) & 1) * 8;
    int r0i = tid >> 2, q0 = (tid & 3);
    int r1i = (tid + 256) >> 2, q1 = ((tid + 256) & 3);

#define MG_STAGE(kc, buf) do {                                                     \
    uint32_t bb = smb + (buf) * 40960;                                             \
    int rows[2] = {r0i, r1i}; int qs[2] = {q0, q1};                                \
    _Pragma("unroll")                                                              \
    for (int m = 0; m < 2; m++) {                                                  \
        int r = rows[m], q = qs[m];                                                \
        int row = rowBase + r; if (row > N-1) row = N-1;                           \
        uint32_t da = bb + r*80 + q*16;                                            \
        size_t ga = (size_t)row*320 + (kc)*32 + q*8;                               \
        CP_ASYNC(da,         Ah + ga);                                             \
        CP_ASYNC(da + 10240, Al + ga);                                             \
        size_t gb = (size_t)(colBase + r)*320 + (kc)*32 + q*8;                     \
        CP_ASYNC(da + 20480, Bh + gb);                                             \
        CP_ASYNC(da + 30720, Bl + gb);                                             \
    } } while (0)

    MG_STAGE(0, 0);
    CP_COMMIT();
    for (int kc = 0; kc < 10; kc++) {
        int buf = kc & 1;
        if (kc < 9) { MG_STAGE(kc + 1, buf ^ 1); CP_COMMIT(); CP_WAIT(1); }
        else CP_WAIT(0);
        __syncthreads();
        uint32_t bb = smb + buf * 40960;
#pragma unroll
        for (int ks = 0; ks < 32; ks += 16) {
            uint32_t ah[2][4], al[2][4], bh[4][4], bl[4][4];
#pragma unroll
            for (int mt = 0; mt < 2; mt++) {
                uint32_t off = bb + ((wm*32 + mt*16 + aRow) * 40 + ks + aK) * 2;
                ldsm_x4(ah[mt], off);
                ldsm_x4(al[mt], off + 10240);
            }
#pragma unroll
            for (int bt = 0; bt < 4; bt++) {
                uint32_t off = bb + 20480 + ((wn*64 + bt*16 + bN) * 40 + ks + bK) * 2;
                ldsm_x4(bh[bt], off);
                ldsm_x4(bl[bt], off + 10240);
            }
#pragma unroll
            for (int pass = 0; pass < 3; pass++)
#pragma unroll
                for (int mt = 0; mt < 2; mt++)
#pragma unroll
                    for (int nt = 0; nt < 8; nt++) {
                        const uint32_t* ap = (pass == 2) ? al[mt] : ah[mt];
                        const uint32_t* bp = (pass == 1) ? &bl[nt>>1][(nt&1)*2]
                                                         : &bh[nt>>1][(nt&1)*2];
                        mma_bf16(acc[mt][nt], ap, bp);
                    }
        }
        __syncthreads();
    }
    int g = lane >> 2, tq = (lane & 3) * 2;
#pragma unroll
    for (int mt = 0; mt < 2; mt++) {
        int r0 = rowBase + wm*32 + mt*16 + g;
#pragma unroll
        for (int nt = 0; nt < 8; nt++) {
            int c0 = colBase + wn*64 + nt*8 + tq;
            float b0 = __ldg(bias + c0), b1 = __ldg(bias + c0 + 1);
            if (r0 < N) {
                out[(size_t)r0*256 + c0]     = acc[mt][nt][0] + b0;
                out[(size_t)r0*256 + c0 + 1] = acc[mt][nt][1] + b1;
            }
            if (r0 + 8 < N) {
                out[(size_t)(r0+8)*256 + c0]     = acc[mt][nt][2] + b0;
                out[(size_t)(r0+8)*256 + c0 + 1] = acc[mt][nt][3] + b1;
            }
        }
    }
}

// ---------------------------------------------------------------------------
// Edge conv1: 384 threads. Warps 0-7 mma (2 per SMSP: warp w -> rows (w&3)*32,
// cols (w>>2)*64). Warps 8-11 build next tile (double buffered R).
// ---------------------------------------------------------------------------
#define EP 136
#define E_SMEM 208896

__device__ __forceinline__ void edge1_build(char* sm, int roff, int tile,
                                            const int* __restrict__ src, int N, int tid2) {
    int r = tid2;
    int local = r & 31;
    int s = local / 10, j = local - s * 10;
    int n = tile * 12 + (r >> 5) * 3 + s;
    if (local < 30 && n < N) {
        int sidx = src[n + j * N];
        const float4* hc4 = reinterpret_cast<const float4*>(g_hcn + (size_t)n * 256);
        const float4* hn4 = reinterpret_cast<const float4*>(g_hcn + (size_t)sidx * 256 + 128);
        char* bh = sm + roff + r * (EP * 2);
        char* bl = bh + 34816;
#pragma unroll 4
        for (int i = 0; i < 32; i++) {
            float4 a = hc4[i], b = hn4[i];
            float v0 = fmaxf(a.x + b.x, 0.f), v1 = fmaxf(a.y + b.y, 0.f);
            float v2 = fmaxf(a.z + b.z, 0.f), v3 = fmaxf(a.w + b.w, 0.f);
            float r0, r1, r2, r3;
            uint2 hh = make_uint2(pack_hi(v0, v1, r0, r1), pack_hi(v2, v3, r2, r3));
            *reinterpret_cast<uint2*>(bh + i * 8) = hh;
            *reinterpret_cast<uint2*>(bl + i * 8) = make_uint2(pack_lo(r0, r1), pack_lo(r2, r3));
        }
    }
    for (int q = tid2; q < 1152; q += 128) {
        int ln = q / 96, o = q - ln * 96, n2 = tile * 12 + ln;
        if (n2 < N) {
            size_t u = (size_t)n2 * 160 + 64 + o;
            reinterpret_cast<uint32_t*>(g_x2h)[u] = reinterpret_cast<const uint32_t*>(g_x1h)[u];
            reinterpret_cast<uint32_t*>(g_x2l)[u] = reinterpret_cast<const uint32_t*>(g_x1l)[u];
        }
    }
}

__global__ void __launch_bounds__(384, 1) edge1_mma(
    const int* __restrict__ src, const float* __restrict__ b2, int N, int ntiles) {
    extern __shared__ char sm[];
    __shared__ float b2s[128];
    int tid = threadIdx.x, lane = tid & 31, warp = tid >> 5;
    if (tid < 128) b2s[tid] = b2[tid];
    for (int idx = tid; idx < 2048; idx += 384) {
        int r = idx >> 4, kq = (idx & 15) * 8;
        *reinterpret_cast<uint4*>(sm + (r*EP + kq)*2) =
            *reinterpret_cast<const uint4*>(g_W2th + r*128 + kq);
        *reinterpret_cast<uint4*>(sm + 34816 + (r*EP + kq)*2) =
            *reinterpret_cast<const uint4*>(g_W2tl + r*128 + kq);
    }
    for (int idx = tid; idx < 2176; idx += 384) {
        int rowsel = idx / 68, u = idx - rowsel * 68;
        int buf = rowsel >> 4, plane = (rowsel >> 3) & 1, ri = rowsel & 7;
        int row = (ri >> 1) * 32 + 30 + (ri & 1);
        *reinterpret_cast<uint32_t*>(sm + 69632 + buf*69632 + plane*34816 + row*(EP*2) + u*4) = 0u;
    }
    if (warp >= 8 && (int)blockIdx.x < ntiles)
        edge1_build(sm, 69632, blockIdx.x, src, N, tid - 256);
    __syncthreads();

    uint32_t smb = smem_u32(sm);
    uint32_t uW2h = smb, uW2l = smb + 34816;
    int aRow = lane & 15, aK = (lane >> 4) * 8;
    int bN_ = ((lane >> 4) << 3) + (lane & 7), bK = ((lane >> 3) & 1) * 8;
    int g = lane >> 2;
    int wm = warp & 3, wn = (warp >> 2) & 1;

    int lt = 0;
    for (int tile = blockIdx.x; tile < ntiles; tile += gridDim.x, lt ^= 1) {
        int roff = 69632 + lt * 69632;
        if (warp < 8) {
            uint32_t uRh = smb + roff, uRl = uRh + 34816;
            float acc[2][8][4];
#pragma unroll
            for (int m = 0; m < 2; m++)
#pragma unroll
                for (int n = 0; n < 8; n++)
#pragma unroll
                    for (int q = 0; q < 4; q++) acc[m][n][q] = 0.f;
#pragma unroll
            for (int ks = 0; ks < 128; ks += 16) {
                uint32_t ah[2][4], al[2][4], bh[4][4], bl[4][4];
#pragma unroll
                for (int mt = 0; mt < 2; mt++) {
                    uint32_t off = ((wm*32 + mt*16 + aRow) * EP + ks + aK) * 2;
                    ldsm_x4(ah[mt], uRh + off);
                    ldsm_x4(al[mt], uRl + off);
                }
#pragma unroll
                for (int bt = 0; bt < 4; bt++) {
                    uint32_t off = ((wn*64 + bt*16 + bN_) * EP + ks + bK) * 2;
                    ldsm_x4(bh[bt], uW2h + off);
                    ldsm_x4(bl[bt], uW2l + off);
                }
#pragma unroll
                for (int pass = 0; pass < 3; pass++)
#pragma unroll
                    for (int mt = 0; mt < 2; mt++)
#pragma unroll
                        for (int nt = 0; nt < 8; nt++) {
                            const uint32_t* ap = (pass == 2) ? al[mt] : ah[mt];
                            const uint32_t* bp = (pass == 1) ? &bl[nt>>1][(nt&1)*2]
                                                             : &bh[nt>>1][(nt&1)*2];
                            mma_bf16(acc[mt][nt], ap, bp);
                        }
            }
            // segment-max epilogue: nodes n0..n0+2 live in this warp's 32 rows
            int n0 = tile * 12 + wm * 3;
#pragma unroll
            for (int nt = 0; nt < 8; nt++) {
                float e0 = acc[0][nt][0], o0 = acc[0][nt][1];
                if (g < 2) { e0 = fmaxf(e0, acc[0][nt][2]); o0 = fmaxf(o0, acc[0][nt][3]); }
                float e1 = (g >= 2) ? acc[0][nt][2] : -FLT_MAX;
                float o1 = (g >= 2) ? acc[0][nt][3] : -FLT_MAX;
                if (g < 4) { e1 = fmaxf(e1, acc[1][nt][0]); o1 = fmaxf(o1, acc[1][nt][1]); }
                float e2 = (g >= 4) ? acc[1][nt][0] : -FLT_MAX;
                float o2 = (g >= 4) ? acc[1][nt][1] : -FLT_MAX;
                if (g < 6) { e2 = fmaxf(e2, acc[1][nt][2]); o2 = fmaxf(o2, acc[1][nt][3]); }
#pragma unroll
                for (int off = 4; off <= 16; off <<= 1) {
                    e0 = fmaxf(e0, __shfl_xor_sync(0xffffffffu, e0, off));
                    o0 = fmaxf(o0, __shfl_xor_sync(0xffffffffu, o0, off));
                    e1 = fmaxf(e1, __shfl_xor_sync(0xffffffffu, e1, off));
                    o1 = fmaxf(o1, __shfl_xor_sync(0xffffffffu, o1, off));
                    e2 = fmaxf(e2, __shfl_xor_sync(0xffffffffu, e2, off));
                    o2 = fmaxf(o2, __shfl_xor_sync(0xffffffffu, o2, off));
                }
                if (lane < 4) {
                    int colb = wn*64 + nt*8 + lane*2;
                    float bce = b2s[colb], bco = b2s[colb+1];
                    float ve[3] = {fmaxf(e0+bce,0.f), fmaxf(e1+bce,0.f), fmaxf(e2+bce,0.f)};
                    float vo[3] = {fmaxf(o0+bco,0.f), fmaxf(o1+bco,0.f), fmaxf(o2+bco,0.f)};
#pragma unroll
                    for (int s = 0; s < 3; s++) {
                        int n = n0 + s;
                        if (n < N) {
                            float r0, r1;
                            uint32_t hh = pack_hi(ve[s], vo[s], r0, r1);
                            size_t u = (size_t)n * 160 + (colb >> 1);
                            reinterpret_cast<uint32_t*>(g_x2h)[u] = hh;
                            reinterpret_cast<uint32_t*>(g_x2l)[u] = pack_lo(r0, r1);
                        }
                    }
                }
            }
        } else {
            int nxt = tile + gridDim.x;
            if (nxt < ntiles)
                edge1_build(sm, 69632 + (lt ^ 1) * 69632, nxt, src, N, tid - 256);
        }
        __syncthreads();
    }
}

// ---------------------------------------------------------------------------
__global__ void edge2_kernel(const int* __restrict__ src, const float* __restrict__ W2s,
                             const float* __restrict__ b2, float* __restrict__ out,
                             int N, int EPN) {
    int gw = (blockIdx.x * blockDim.x + threadIdx.x) >> 5;
    int lane = threadIdx.x & 31;
    if (gw >= N) return;
    int n = gw;
    int b0 = lane & 1, b1 = (lane >> 1) & 1;
    int c = 2*b0 + b1;
    float4 wr0 = *reinterpret_cast<const float4*>(W2s + (lane*4)*4);
    float4 wr1 = *reinterpret_cast<const float4*>(W2s + (lane*4+1)*4);
    float4 wr2 = *reinterpret_cast<const float4*>(W2s + (lane*4+2)*4);
    float4 wr3 = *reinterpret_cast<const float4*>(W2s + (lane*4+3)*4);
    float bc = __ldg(b2 + c);
    float4 hc = *reinterpret_cast<const float4*>(&g_hcn[(size_t)n*256 + lane*4]);
    float mx = -FLT_MAX;
#pragma unroll
    for (int j = 0; j < 10; j++) {
        int s = src[n + j*N];
        float4 hb = *reinterpret_cast<const float4*>(&g_hcn[(size_t)s*256 + 128 + lane*4]);
        float r0 = fmaxf(hc.x+hb.x,0.f), r1 = fmaxf(hc.y+hb.y,0.f);
        float r2 = fmaxf(hc.z+hb.z,0.f), r3 = fmaxf(hc.w+hb.w,0.f);
        float y0 = r0*wr0.x + r1*wr1.x + r2*wr2.x + r3*wr3.x;
        float y1 = r0*wr0.y + r1*wr1.y + r2*wr2.y + r3*wr3.y;
        float y2 = r0*wr0.z + r1*wr1.z + r2*wr2.z + r3*wr3.z;
        float y3 = r0*wr0.w + r1*wr1.w + r2*wr2.w + r3*wr3.w;
        float t0 = __shfl_xor_sync(0xffffffffu, b0 ? y0 : y2, 1);
        float t1 = __shfl_xor_sync(0xffffffffu, b0 ? y1 : y3, 1);
        float p0 = (b0 ? y2 : y0) + t0;
        float p1 = (b0 ? y3 : y1) + t1;
        float t2 = __shfl_xor_sync(0xffffffffu, b1 ? p0 : p1, 2);
        float z  = (b1 ? p1 : p0) + t2;
        z += __shfl_xor_sync(0xffffffffu, z, 4);
        z += __shfl_xor_sync(0xffffffffu, z, 8);
        z += __shfl_xor_sync(0xffffffffu, z, 16);
        mx = fmaxf(mx, z);
    }
    if (lane < 4) out[(size_t)n*4 + c] = (mx + bc) * g_sinv[n];
}

// ---------------------------------------------------------------------------
extern "C" void kernel_launch(void* const* d_in, const int* in_sizes, int n_in,
                              void* d_out, int out_size) {
    const float* t        = (const float*)d_in[0];
    const float* obj_x    = (const float*)d_in[1];
    const float* obj_geo  = (const float*)d_in[2];
    const float* wall     = (const float*)d_in[3];
    const int*   category = (const int*)d_in[4];
    const int*   batch_idx= (const int*)d_in[5];
    const int*   src      = (const int*)d_in[6];
    const float* embed_W  = (const float*)d_in[8];
    const float* gfp_W    = (const float*)d_in[9];
    const float* sW       = (const float*)d_in[10];
    const float* sb       = (const float*)d_in[11];
    const float* w1       = (const float*)d_in[12];
    const float* wb1      = (const float*)d_in[13];
    const float* w2       = (const float*)d_in[14];
    const float* wb2      = (const float*)d_in[15];
    const float* i1       = (const float*)d_in[16];
    const float* ib1      = (const float*)d_in[17];
    const float* i2       = (const float*)d_in[18];
    const float* ib2      = (const float*)d_in[19];
    const float* m1W1     = (const float*)d_in[20];
    const float* m1b1     = (const float*)d_in[21];
    const float* m1W2     = (const float*)d_in[22];
    const float* m1b2     = (const float*)d_in[23];
    const float* m2W1     = (const float*)d_in[24];
    const float* m2b1     = (const float*)d_in[25];
    const float* m2W2     = (const float*)d_in[26];
    const float* m2b2     = (const float*)d_in[27];

    int N = in_sizes[0], E = in_sizes[6], B = in_sizes[3] / 2;
    int EPN = E / N;
    int nt12 = (N + 11) / 12;

    float *p_h, *p_hcn, *p_bc1, *p_bc2;
    __nv_bfloat16 *p_x1h, *p_x1l, *p_x2h, *p_x2l, *p_W1h, *p_W1l, *p_W2h, *p_W2l;
    cudaGetSymbolAddress((void**)&p_h, g_h);
    cudaGetSymbolAddress((void**)&p_hcn, g_hcn);
    cudaGetSymbolAddress((void**)&p_bc1, g_bc1);
    cudaGetSymbolAddress((void**)&p_bc2, g_bc2);
    cudaGetSymbolAddress((void**)&p_x1h, g_x1h);
    cudaGetSymbolAddress((void**)&p_x1l, g_x1l);
    cudaGetSymbolAddress((void**)&p_x2h, g_x2h);
    cudaGetSymbolAddress((void**)&p_x2l, g_x2l);
    cudaGetSymbolAddress((void**)&p_W1h, g_Wt1h);
    cudaGetSymbolAddress((void**)&p_W1l, g_Wt1l);
    cudaGetSymbolAddress((void**)&p_W2h, g_Wt2h);
    cudaGetSymbolAddress((void**)&p_W2l, g_Wt2l);

    cudaFuncSetAttribute(mma_gemm, cudaFuncAttributeMaxDynamicSharedMemorySize, MG_SMEM);
    cudaFuncSetAttribute(edge1_mma, cudaFuncAttributeMaxDynamicSharedMemorySize, E_SMEM);

    setup_weights<<<704, 256>>>(m1W1, m1b1, m2W1, m2b1, m1W2);          // 1
    setup_wall<<<(B + 3) / 4, 256>>>(wall, w1, wb1, w2, wb2, B);         // 2
    node_kernel<<<(N + 31) / 32, 256>>>(t, obj_x, obj_geo, category,     // 3
                                        batch_idx, embed_W, gfp_W, sW, sb, i1, ib1, N);
    gemm128<<<(N + 127) / 128, 256>>>(p_h, i2, ib2, N);                  // 4
    {
        dim3 g((N + 127) / 128, 2);
        mma_gemm<<<g, 256, MG_SMEM>>>(p_x1h, p_x1l, p_W1h, p_W1l, p_bc1, p_hcn, N); // 5
    }
    edge1_mma<<<148, 384, E_SMEM>>>(src, m1b2, N, nt12);                 // 6 (profiled)
    {
        dim3 g((N + 127) / 128, 2);
        mma_gemm<<<g, 256, MG_SMEM>>>(p_x2h, p_x2l, p_W2h, p_W2l, p_bc2, p_hcn, N); // 7
    }
    edge2_kernel<<<(N + 7) / 8, 256>>>(src, m2W2, m2b2, (float*)d_out, N, EPN);     // 8
}

// round 13
// speedup vs baseline: 1.3525x; 1.3525x over previous
#include <cuda_runtime.h>
#include <cuda_fp16.h>
#include <math.h>
#include <float.h>
#include <stdint.h>

#define NMAX 50000
#define BMAX 1024

__device__ float g_wall_h[BMAX * 64];
__device__ float g_h[NMAX * 128];
__device__ float g_hcn[NMAX * 256];
__device__ float g_sinv[NMAX];
__device__ __align__(16) __half g_x1h[NMAX * 320];
__device__ __align__(16) __half g_x2h[NMAX * 320];
__device__ __align__(16) __half g_Wt1h[256 * 320];
__device__ __align__(16) __half g_Wt1l[256 * 320];
__device__ __align__(16) __half g_Wt2h[256 * 320];
__device__ __align__(16) __half g_Wt2l[256 * 320];
__device__ __align__(16) __half g_W2th[128 * 128];
__device__ __align__(16) __half g_W2tl[128 * 128];
__device__ float g_bc1[256];
__device__ float g_bc2[256];

// ---- helpers ----
__device__ __forceinline__ uint32_t smem_u32(const void* p) {
    uint32_t a;
    asm("{ .reg .u64 t; cvta.to.shared.u64 t, %1; cvt.u32.u64 %0, t; }" : "=r"(a) : "l"(p));
    return a;
}
__device__ __forceinline__ void ldsm_x4(uint32_t* r, uint32_t addr) {
    asm volatile("ldmatrix.sync.aligned.m8n8.x4.shared.b16 {%0,%1,%2,%3}, [%4];"
                 : "=r"(r[0]), "=r"(r[1]), "=r"(r[2]), "=r"(r[3]) : "r"(addr));
}
__device__ __forceinline__ void mma_f16(float* c, const uint32_t* a, const uint32_t* b) {
    asm volatile("mma.sync.aligned.m16n8k16.row.col.f32.f16.f16.f32 "
                 "{%0,%1,%2,%3}, {%4,%5,%6,%7}, {%8,%9}, {%0,%1,%2,%3};"
                 : "+f"(c[0]), "+f"(c[1]), "+f"(c[2]), "+f"(c[3])
                 : "r"(a[0]), "r"(a[1]), "r"(a[2]), "r"(a[3]), "r"(b[0]), "r"(b[1]));
}
#define CP_ASYNC(dst, src) \
    asm volatile("cp.async.cg.shared.global [%0], [%1], 16;" :: "r"(dst), "l"(src) : "memory")
#define CP_COMMIT() asm volatile("cp.async.commit_group;" ::: "memory")
#define CP_WAIT(n)  asm volatile("cp.async.wait_group %0;" :: "n"(n) : "memory")

__device__ __forceinline__ uint32_t packh2(float a, float b) {
    __half2 p = __floats2half2_rn(a, b);
    return *reinterpret_cast<uint32_t*>(&p);
}
__device__ __forceinline__ unsigned long long dup2(float x) {
    unsigned long long r; asm("mov.b64 %0, {%1, %1};" : "=l"(r) : "f"(x)); return r;
}
__device__ __forceinline__ void ffma2(unsigned long long& d, unsigned long long a, unsigned long long b) {
    asm("fma.rn.f32x2 %0, %1, %2, %0;" : "+l"(d) : "l"(a), "l"(b));
}
__device__ __forceinline__ float2 unpack2(unsigned long long p) {
    float lo, hi; asm("mov.b64 {%0, %1}, %2;" : "=f"(lo), "=f"(hi) : "l"(p)); return make_float2(lo, hi);
}

// ---------------------------------------------------------------------------
__global__ void __launch_bounds__(256) setup_weights(
    const float* __restrict__ m1W1, const float* __restrict__ m1b1,
    const float* __restrict__ m2W1, const float* __restrict__ m2b1,
    const float* __restrict__ m1W2) {
    int b = blockIdx.x, tid = threadIdx.x;
    if (b < 640) {
        int sel = b >= 320;
        const float* W1 = sel ? m2W1 : m1W1;
        const float* b1 = sel ? m2b1 : m1b1;
        __half* Wh = sel ? g_Wt2h : g_Wt1h;
        __half* Wl = sel ? g_Wt2l : g_Wt1l;
        float* bc = sel ? g_bc2 : g_bc1;
        int idx = (sel ? b - 320 : b) * 256 + tid;
        if (idx < 256 * 320) {
            int c = idx / 320, k = idx - c * 320;
            float v = (c < 128) ? (W1[k*128+c] - W1[(k+320)*128+c]) : W1[(k+320)*128+(c-128)];
            __half h = __float2half_rn(v);
            Wh[idx] = h; Wl[idx] = __float2half_rn(v - __half2float(h));
        }
        if (idx < 256) bc[idx] = (idx < 128) ? b1[idx] : 0.f;
    } else {
        int idx = (b - 640) * 256 + tid;
        int c = idx >> 7, k = idx & 127;
        float v = m1W2[k*128+c];
        __half h = __float2half_rn(v);
        g_W2th[idx] = h; g_W2tl[idx] = __float2half_rn(v - __half2float(h));
    }
}

__global__ void __launch_bounds__(256) setup_wall(
    const float* __restrict__ wall, const float* __restrict__ w1,
    const float* __restrict__ wb1, const float* __restrict__ w2,
    const float* __restrict__ wb2, int B) {
    __shared__ float h[4][64];
    int tid = threadIdx.x;
    int row = blockIdx.x * 4 + (tid >> 6), k = tid & 63, rr = tid >> 6;
    if (row < B)
        h[rr][k] = fmaxf(wall[row*2]*w1[k] + wall[row*2+1]*w1[64+k] + wb1[k], 0.f);
    __syncthreads();
    if (row < B) {
        float acc = wb2[k];
#pragma unroll 8
        for (int i = 0; i < 64; i++) acc += h[rr][i] * w2[i*64+k];
        g_wall_h[row*64+k] = fmaxf(acc, 0.f);
    }
}

// ---------------------------------------------------------------------------
__global__ void __launch_bounds__(256) node_kernel(
    const float* __restrict__ t, const float* __restrict__ obj_x, const float* __restrict__ obj_geo,
    const int* __restrict__ category, const int* __restrict__ batch_idx,
    const float* __restrict__ embed_W, const float* __restrict__ gfp_W,
    const float* __restrict__ sW, const float* __restrict__ sb,
    const float* __restrict__ i1, const float* __restrict__ ib1, int N) {
    __shared__ float sWsh[64*64], i1sh[6*128], embsh[10*64], gfpsh[32], ib1sh[128], sbsh[64];
    __shared__ float2 gd[8][64];
    int tid = threadIdx.x, warp = tid >> 5, lane = tid & 31;
    for (int i = tid; i < 4096; i += 256) sWsh[i] = sW[i];
    for (int i = tid; i < 768; i += 256) i1sh[i] = i1[i];
    for (int i = tid; i < 640; i += 256) embsh[i] = embed_W[i];
    if (tid < 32) gfpsh[tid] = gfp_W[tid];
    if (tid < 128) ib1sh[tid] = ib1[tid];
    if (tid < 64) sbsh[tid] = sb[tid];
    __syncthreads();
    int base = blockIdx.x * 32;
#pragma unroll
    for (int it = 0; it < 4; it++) {
        int n = base + it * 8 + warp;
        if (n >= N) continue;
        float tv = __ldg(t + n);
        float p = tv * gfpsh[lane] * 6.283185307179586f;
        float sv = sinf(p), cv = cosf(p);
        gd[warp][lane] = make_float2(sv, sv);
        gd[warp][lane+32] = make_float2(cv, cv);
        int cat = category[n], bi = batch_idx[n];
        uint32_t* x1hu = reinterpret_cast<uint32_t*>(g_x1h);
        size_t nb = (size_t)n * 160;
        x1hu[nb + 64 + lane] = packh2(fmaxf(embsh[cat*64 + 2*lane], 0.f),
                                      fmaxf(embsh[cat*64 + 2*lane + 1], 0.f));
        x1hu[nb + 128 + lane] = packh2(g_wall_h[bi*64 + 2*lane], g_wall_h[bi*64 + 2*lane + 1]);
        if (lane == 0) {
            const float LN25 = 3.2188758248682006f;
            float stdv = sqrtf((expf(2.f*tv*LN25) - 1.f) / (2.f*LN25));
            g_sinv[n] = 1.f / (stdv + 1e-7f);
        }
        float xv = 0.f;
        if (lane < 4) xv = obj_x[n*4+lane]; else if (lane < 6) xv = obj_geo[n*2+lane-4];
        float4 a = *reinterpret_cast<const float4*>(ib1sh + lane*4);
#pragma unroll
        for (int i = 0; i < 6; i++) {
            float xi = __shfl_sync(0xffffffffu, xv, i);
            float4 w = *reinterpret_cast<const float4*>(i1sh + i*128 + lane*4);
            a.x += xi*w.x; a.y += xi*w.y; a.z += xi*w.z; a.w += xi*w.w;
        }
        a.x = fmaxf(a.x,0.f); a.y = fmaxf(a.y,0.f); a.z = fmaxf(a.z,0.f); a.w = fmaxf(a.w,0.f);
        *reinterpret_cast<float4*>(g_h + (size_t)n*128 + lane*4) = a;
        __syncwarp();
        unsigned long long accp = *reinterpret_cast<const unsigned long long*>(sbsh + lane*2);
#pragma unroll 8
        for (int i = 0; i < 64; i++)
            ffma2(accp, *reinterpret_cast<const unsigned long long*>(&gd[warp][i]),
                  *reinterpret_cast<const unsigned long long*>(sWsh + i*64 + lane*2));
        float2 v = unpack2(accp);
        x1hu[nb + 96 + lane] = packh2(fmaxf(v.x,0.f), fmaxf(v.y,0.f));
        __syncwarp();
    }
}

// ---------------------------------------------------------------------------
__global__ void __launch_bounds__(256, 2) gemm128(
    const float* __restrict__ A, const float* __restrict__ W,
    const float* __restrict__ bias, int N) {
    __shared__ float At[16][132], Ws[16][128];
    int tid = threadIdx.x, rowBase = blockIdx.x * 128;
    int rg = tid >> 4, cg = tid & 15;
    unsigned long long acc[8][4];
#pragma unroll
    for (int r = 0; r < 8; r++) for (int c = 0; c < 4; c++) acc[r][c] = 0ULL;
    for (int kc = 0; kc < 128; kc += 16) {
        __syncthreads();
#pragma unroll
        for (int i = 0; i < 2; i++) {
            int idx = tid + i*256, r = idx >> 2, kq = (idx & 3) << 2;
            int row = rowBase + r; if (row > N-1) row = N-1;
            float4 v = *reinterpret_cast<const float4*>(A + (size_t)row*128 + kc + kq);
            At[kq][r] = v.x; At[kq+1][r] = v.y; At[kq+2][r] = v.z; At[kq+3][r] = v.w;
        }
#pragma unroll
        for (int i = 0; i < 2; i++) {
            int idx = tid + i*256, k = idx >> 5, c4 = (idx & 31) << 2;
            *reinterpret_cast<float4*>(&Ws[k][c4]) =
                *reinterpret_cast<const float4*>(W + (size_t)(kc+k)*128 + c4);
        }
        __syncthreads();
#pragma unroll
        for (int kk = 0; kk < 16; kk++) {
            float4 a0 = *reinterpret_cast<const float4*>(&At[kk][rg*8]);
            float4 a1 = *reinterpret_cast<const float4*>(&At[kk][rg*8+4]);
            ulonglong2 w0 = *reinterpret_cast<const ulonglong2*>(&Ws[kk][cg*8]);
            ulonglong2 w1 = *reinterpret_cast<const ulonglong2*>(&Ws[kk][cg*8+4]);
            unsigned long long ad[8] = {dup2(a0.x),dup2(a0.y),dup2(a0.z),dup2(a0.w),
                                        dup2(a1.x),dup2(a1.y),dup2(a1.z),dup2(a1.w)};
#pragma unroll
            for (int r = 0; r < 8; r++) {
                ffma2(acc[r][0], ad[r], w0.x); ffma2(acc[r][1], ad[r], w0.y);
                ffma2(acc[r][2], ad[r], w1.x); ffma2(acc[r][3], ad[r], w1.y);
            }
        }
    }
    float4 b0 = *reinterpret_cast<const float4*>(bias + cg*8);
    float4 b1 = *reinterpret_cast<const float4*>(bias + cg*8 + 4);
    uint32_t* x1hu = reinterpret_cast<uint32_t*>(g_x1h);
#pragma unroll
    for (int r = 0; r < 8; r++) {
        int row = rowBase + rg*8 + r;
        if (row < N) {
            float2 v0 = unpack2(acc[r][0]), v1 = unpack2(acc[r][1]);
            float2 v2 = unpack2(acc[r][2]), v3 = unpack2(acc[r][3]);
            uint32_t hh[4] = {
                packh2(fmaxf(v0.x+b0.x,0.f), fmaxf(v0.y+b0.y,0.f)),
                packh2(fmaxf(v1.x+b0.z,0.f), fmaxf(v1.y+b0.w,0.f)),
                packh2(fmaxf(v2.x+b1.x,0.f), fmaxf(v2.y+b1.y,0.f)),
                packh2(fmaxf(v3.x+b1.z,0.f), fmaxf(v3.y+b1.w,0.f))};
            size_t u = (size_t)row * 160 + cg * 4;
            *reinterpret_cast<uint2*>(x1hu + u)     = make_uint2(hh[0], hh[1]);
            *reinterpret_cast<uint2*>(x1hu + u + 2) = make_uint2(hh[2], hh[3]);
        }
    }
}

// ---------------------------------------------------------------------------
// mma.sync GEMM fp16: A single plane, W hi/lo 2-term. cp.async double buffered.
// ---------------------------------------------------------------------------
#define MG_SMEM 61440
__global__ void __launch_bounds__(256, 2) mma_gemm(
    const __half* __restrict__ Ah,
    const __half* __restrict__ Bh, const __half* __restrict__ Bl,
    const float* __restrict__ bias, float* __restrict__ out, int N) {
    extern __shared__ char sm[];
    uint32_t smb = smem_u32(sm);
    int tid = threadIdx.x, lane = tid & 31, warp = tid >> 5;
    int wm = warp & 3, wn = warp >> 2;
    int rowBase = blockIdx.x * 128, colBase = blockIdx.y * 128;
    float acc[2][8][4];
#pragma unroll
    for (int m = 0; m < 2; m++) for (int n = 0; n < 8; n++)
        for (int q = 0; q < 4; q++) acc[m][n][q] = 0.f;
    int aRow = lane & 15, aK = (lane >> 4) * 8;
    int bN = ((lane >> 4) << 3) + (lane & 7), bK = ((lane >> 3) & 1) * 8;
    int r0i = tid >> 2, q0 = (tid & 3);
    int r1i = (tid + 256) >> 2, q1 = ((tid + 256) & 3);

#define MG_STAGE(kc, buf) do {                                                     \
    uint32_t bb = smb + (buf) * 30720;                                             \
    int rows[2] = {r0i, r1i}; int qs[2] = {q0, q1};                                \
    _Pragma("unroll")                                                              \
    for (int m = 0; m < 2; m++) {                                                  \
        int r = rows[m], q = qs[m];                                                \
        int row = rowBase + r; if (row > N-1) row = N-1;                           \
        uint32_t da = bb + r*80 + q*16;                                            \
        CP_ASYNC(da, Ah + (size_t)row*320 + (kc)*32 + q*8);                        \
        size_t gb = (size_t)(colBase + r)*320 + (kc)*32 + q*8;                     \
        CP_ASYNC(da + 10240, Bh + gb);                                             \
        CP_ASYNC(da + 20480, Bl + gb);                                             \
    } } while (0)

    MG_STAGE(0, 0);
    CP_COMMIT();
    for (int kc = 0; kc < 10; kc++) {
        int buf = kc & 1;
        if (kc < 9) { MG_STAGE(kc + 1, buf ^ 1); CP_COMMIT(); CP_WAIT(1); }
        else CP_WAIT(0);
        __syncthreads();
        uint32_t bb = smb + buf * 30720;
#pragma unroll
        for (int ks = 0; ks < 32; ks += 16) {
            uint32_t ah[2][4], bh[4][4], bl[4][4];
#pragma unroll
            for (int mt = 0; mt < 2; mt++)
                ldsm_x4(ah[mt], bb + ((wm*32 + mt*16 + aRow) * 40 + ks + aK) * 2);
#pragma unroll
            for (int bt = 0; bt < 4; bt++) {
                uint32_t off = bb + 10240 + ((wn*64 + bt*16 + bN) * 40 + ks + bK) * 2;
                ldsm_x4(bh[bt], off);
                ldsm_x4(bl[bt], off + 10240);
            }
#pragma unroll
            for (int pass = 0; pass < 2; pass++)
#pragma unroll
                for (int mt = 0; mt < 2; mt++)
#pragma unroll
                    for (int nt = 0; nt < 8; nt++) {
                        const uint32_t* bp = pass ? &bl[nt>>1][(nt&1)*2]
                                                  : &bh[nt>>1][(nt&1)*2];
                        mma_f16(acc[mt][nt], ah[mt], bp);
                    }
        }
        __syncthreads();
    }
    int g = lane >> 2, tq = (lane & 3) * 2;
#pragma unroll
    for (int mt = 0; mt < 2; mt++) {
        int r0 = rowBase + wm*32 + mt*16 + g;
#pragma unroll
        for (int nt = 0; nt < 8; nt++) {
            int c0 = colBase + wn*64 + nt*8 + tq;
            float b0 = __ldg(bias + c0), b1 = __ldg(bias + c0 + 1);
            if (r0 < N) {
                out[(size_t)r0*256 + c0]     = acc[mt][nt][0] + b0;
                out[(size_t)r0*256 + c0 + 1] = acc[mt][nt][1] + b1;
            }
            if (r0 + 8 < N) {
                out[(size_t)(r0+8)*256 + c0]     = acc[mt][nt][2] + b0;
                out[(size_t)(r0+8)*256 + c0 + 1] = acc[mt][nt][3] + b1;
            }
        }
    }
}

// ---------------------------------------------------------------------------
// Edge conv1 fp16: 384 threads, warps 0-7 mma (2/SMSP), 8-11 builders.
// smem: W2h | W2l | R0 | R1 (each 34816B, pitch 136 halfs).
// ---------------------------------------------------------------------------
#define EP 136
#define E_SMEM 139264

__device__ __forceinline__ void edge1_build(char* sm, int roff, int tile,
                                            const int* __restrict__ src, int N, int tid2) {
    int r = tid2;
    int local = r & 31;
    int s = local / 10, j = local - s * 10;
    int n = tile * 12 + (r >> 5) * 3 + s;
    if (local < 30 && n < N) {
        int sidx = src[n + j * N];
        const float4* hc4 = reinterpret_cast<const float4*>(g_hcn + (size_t)n * 256);
        const float4* hn4 = reinterpret_cast<const float4*>(g_hcn + (size_t)sidx * 256 + 128);
        char* bh = sm + roff + r * (EP * 2);
#pragma unroll 4
        for (int i = 0; i < 32; i++) {
            float4 a = hc4[i], b = hn4[i];
            *reinterpret_cast<uint2*>(bh + i * 8) = make_uint2(
                packh2(fmaxf(a.x + b.x, 0.f), fmaxf(a.y + b.y, 0.f)),
                packh2(fmaxf(a.z + b.z, 0.f), fmaxf(a.w + b.w, 0.f)));
        }
    }
    for (int q = tid2; q < 1152; q += 128) {
        int ln = q / 96, o = q - ln * 96, n2 = tile * 12 + ln;
        if (n2 < N) {
            size_t u = (size_t)n2 * 160 + 64 + o;
            reinterpret_cast<uint32_t*>(g_x2h)[u] = reinterpret_cast<const uint32_t*>(g_x1h)[u];
        }
    }
}

__global__ void __launch_bounds__(384, 1) edge1_mma(
    const int* __restrict__ src, const float* __restrict__ b2, int N, int ntiles) {
    extern __shared__ char sm[];
    __shared__ float b2s[128];
    int tid = threadIdx.x, lane = tid & 31, warp = tid >> 5;
    if (tid < 128) b2s[tid] = b2[tid];
    // W2 hi/lo preload: 128 rows x 16 chunks of 8 halfs (FIXED from R12's bug)
    for (int idx = tid; idx < 2048; idx += 384) {
        int r = idx >> 4, kq = (idx & 15) * 8;
        *reinterpret_cast<uint4*>(sm + (r*EP + kq)*2) =
            *reinterpret_cast<const uint4*>(g_W2th + r*128 + kq);
        *reinterpret_cast<uint4*>(sm + 34816 + (r*EP + kq)*2) =
            *reinterpret_cast<const uint4*>(g_W2tl + r*128 + kq);
    }
    // zero unused R rows (local 30,31 of each 32-row group), both buffers
    for (int idx = tid; idx < 1088; idx += 384) {
        int rowsel = idx / 68, u = idx - rowsel * 68;
        int buf = rowsel >> 3, ri = rowsel & 7;
        int row = (ri >> 1) * 32 + 30 + (ri & 1);
        *reinterpret_cast<uint32_t*>(sm + 69632 + buf*34816 + row*(EP*2) + u*4) = 0u;
    }
    if (warp >= 8 && (int)blockIdx.x < ntiles)
        edge1_build(sm, 69632, blockIdx.x, src, N, tid - 256);
    __syncthreads();

    uint32_t smb = smem_u32(sm);
    uint32_t uW2h = smb, uW2l = smb + 34816;
    int aRow = lane & 15, aK = (lane >> 4) * 8;
    int bN_ = ((lane >> 4) << 3) + (lane & 7), bK = ((lane >> 3) & 1) * 8;
    int g = lane >> 2;
    int wm = warp & 3, wn = (warp >> 2) & 1;

    int lt = 0;
    for (int tile = blockIdx.x; tile < ntiles; tile += gridDim.x, lt ^= 1) {
        int roff = 69632 + lt * 34816;
        if (warp < 8) {
            uint32_t uR = smb + roff;
            float acc[2][8][4];
#pragma unroll
            for (int m = 0; m < 2; m++)
#pragma unroll
                for (int n = 0; n < 8; n++)
#pragma unroll
                    for (int q = 0; q < 4; q++) acc[m][n][q] = 0.f;
#pragma unroll
            for (int ks = 0; ks < 128; ks += 16) {
                uint32_t ah[2][4], bh[4][4], bl[4][4];
#pragma unroll
                for (int mt = 0; mt < 2; mt++)
                    ldsm_x4(ah[mt], uR + ((wm*32 + mt*16 + aRow) * EP + ks + aK) * 2);
#pragma unroll
                for (int bt = 0; bt < 4; bt++) {
                    uint32_t off = ((wn*64 + bt*16 + bN_) * EP + ks + bK) * 2;
                    ldsm_x4(bh[bt], uW2h + off);
                    ldsm_x4(bl[bt], uW2l + off);
                }
#pragma unroll
                for (int pass = 0; pass < 2; pass++)
#pragma unroll
                    for (int mt = 0; mt < 2; mt++)
#pragma unroll
                        for (int nt = 0; nt < 8; nt++) {
                            const uint32_t* bp = pass ? &bl[nt>>1][(nt&1)*2]
                                                      : &bh[nt>>1][(nt&1)*2];
                            mma_f16(acc[mt][nt], ah[mt], bp);
                        }
            }
            int n0 = tile * 12 + wm * 3;
#pragma unroll
            for (int nt = 0; nt < 8; nt++) {
                float e0 = acc[0][nt][0], o0 = acc[0][nt][1];
                if (g < 2) { e0 = fmaxf(e0, acc[0][nt][2]); o0 = fmaxf(o0, acc[0][nt][3]); }
                float e1 = (g >= 2) ? acc[0][nt][2] : -FLT_MAX;
                float o1 = (g >= 2) ? acc[0][nt][3] : -FLT_MAX;
                if (g < 4) { e1 = fmaxf(e1, acc[1][nt][0]); o1 = fmaxf(o1, acc[1][nt][1]); }
                float e2 = (g >= 4) ? acc[1][nt][0] : -FLT_MAX;
                float o2 = (g >= 4) ? acc[1][nt][1] : -FLT_MAX;
                if (g < 6) { e2 = fmaxf(e2, acc[1][nt][2]); o2 = fmaxf(o2, acc[1][nt][3]); }
#pragma unroll
                for (int off = 4; off <= 16; off <<= 1) {
                    e0 = fmaxf(e0, __shfl_xor_sync(0xffffffffu, e0, off));
                    o0 = fmaxf(o0, __shfl_xor_sync(0xffffffffu, o0, off));
                    e1 = fmaxf(e1, __shfl_xor_sync(0xffffffffu, e1, off));
                    o1 = fmaxf(o1, __shfl_xor_sync(0xffffffffu, o1, off));
                    e2 = fmaxf(e2, __shfl_xor_sync(0xffffffffu, e2, off));
                    o2 = fmaxf(o2, __shfl_xor_sync(0xffffffffu, o2, off));
                }
                if (lane < 4) {
                    int colb = wn*64 + nt*8 + lane*2;
                    float bce = b2s[colb], bco = b2s[colb+1];
                    float ve[3] = {fmaxf(e0+bce,0.f), fmaxf(e1+bce,0.f), fmaxf(e2+bce,0.f)};
                    float vo[3] = {fmaxf(o0+bco,0.f), fmaxf(o1+bco,0.f), fmaxf(o2+bco,0.f)};
#pragma unroll
                    for (int s = 0; s < 3; s++) {
                        int n = n0 + s;
                        if (n < N)
                            reinterpret_cast<uint32_t*>(g_x2h)[(size_t)n * 160 + (colb >> 1)] =
                                packh2(ve[s], vo[s]);
                    }
                }
            }
        } else {
            int nxt = tile + gridDim.x;
            if (nxt < ntiles)
                edge1_build(sm, 69632 + (lt ^ 1) * 34816, nxt, src, N, tid - 256);
        }
        __syncthreads();
    }
}

// ---------------------------------------------------------------------------
__global__ void edge2_kernel(const int* __restrict__ src, const float* __restrict__ W2s,
                             const float* __restrict__ b2, float* __restrict__ out,
                             int N, int EPN) {
    int gw = (blockIdx.x * blockDim.x + threadIdx.x) >> 5;
    int lane = threadIdx.x & 31;
    if (gw >= N) return;
    int n = gw;
    int b0 = lane & 1, b1 = (lane >> 1) & 1;
    int c = 2*b0 + b1;
    float4 wr0 = *reinterpret_cast<const float4*>(W2s + (lane*4)*4);
    float4 wr1 = *reinterpret_cast<const float4*>(W2s + (lane*4+1)*4);
    float4 wr2 = *reinterpret_cast<const float4*>(W2s + (lane*4+2)*4);
    float4 wr3 = *reinterpret_cast<const float4*>(W2s + (lane*4+3)*4);
    float bc = __ldg(b2 + c);
    float4 hc = *reinterpret_cast<const float4*>(&g_hcn[(size_t)n*256 + lane*4]);
    float mx = -FLT_MAX;
#pragma unroll
    for (int j = 0; j < 10; j++) {
        int s = src[n + j*N];
        float4 hb = *reinterpret_cast<const float4*>(&g_hcn[(size_t)s*256 + 128 + lane*4]);
        float r0 = fmaxf(hc.x+hb.x,0.f), r1 = fmaxf(hc.y+hb.y,0.f);
        float r2 = fmaxf(hc.z+hb.z,0.f), r3 = fmaxf(hc.w+hb.w,0.f);
        float y0 = r0*wr0.x + r1*wr1.x + r2*wr2.x + r3*wr3.x;
        float y1 = r0*wr0.y + r1*wr1.y + r2*wr2.y + r3*wr3.y;
        float y2 = r0*wr0.z + r1*wr1.z + r2*wr2.z + r3*wr3.z;
        float y3 = r0*wr0.w + r1*wr1.w + r2*wr2.w + r3*wr3.w;
        float t0 = __shfl_xor_sync(0xffffffffu, b0 ? y0 : y2, 1);
        float t1 = __shfl_xor_sync(0xffffffffu, b0 ? y1 : y3, 1);
        float p0 = (b0 ? y2 : y0) + t0;
        float p1 = (b0 ? y3 : y1) + t1;
        float t2 = __shfl_xor_sync(0xffffffffu, b1 ? p0 : p1, 2);
        float z  = (b1 ? p1 : p0) + t2;
        z += __shfl_xor_sync(0xffffffffu, z, 4);
        z += __shfl_xor_sync(0xffffffffu, z, 8);
        z += __shfl_xor_sync(0xffffffffu, z, 16);
        mx = fmaxf(mx, z);
    }
    if (lane < 4) out[(size_t)n*4 + c] = (mx + bc) * g_sinv[n];
}

// ---------------------------------------------------------------------------
extern "C" void kernel_launch(void* const* d_in, const int* in_sizes, int n_in,
                              void* d_out, int out_size) {
    const float* t        = (const float*)d_in[0];
    const float* obj_x    = (const float*)d_in[1];
    const float* obj_geo  = (const float*)d_in[2];
    const float* wall     = (const float*)d_in[3];
    const int*   category = (const int*)d_in[4];
    const int*   batch_idx= (const int*)d_in[5];
    const int*   src      = (const int*)d_in[6];
    const float* embed_W  = (const float*)d_in[8];
    const float* gfp_W    = (const float*)d_in[9];
    const float* sW       = (const float*)d_in[10];
    const float* sb       = (const float*)d_in[11];
    const float* w1       = (const float*)d_in[12];
    const float* wb1      = (const float*)d_in[13];
    const float* w2       = (const float*)d_in[14];
    const float* wb2      = (const float*)d_in[15];
    const float* i1       = (const float*)d_in[16];
    const float* ib1      = (const float*)d_in[17];
    const float* i2       = (const float*)d_in[18];
    const float* ib2      = (const float*)d_in[19];
    const float* m1W1     = (const float*)d_in[20];
    const float* m1b1     = (const float*)d_in[21];
    const float* m1W2     = (const float*)d_in[22];
    const float* m1b2     = (const float*)d_in[23];
    const float* m2W1     = (const float*)d_in[24];
    const float* m2b1     = (const float*)d_in[25];
    const float* m2W2     = (const float*)d_in[26];
    const float* m2b2     = (const float*)d_in[27];

    int N = in_sizes[0], E = in_sizes[6], B = in_sizes[3] / 2;
    int EPN = E / N;
    int nt12 = (N + 11) / 12;

    float *p_h, *p_hcn, *p_bc1, *p_bc2;
    __half *p_x1h, *p_x2h, *p_W1h, *p_W1l, *p_W2h, *p_W2l;
    cudaGetSymbolAddress((void**)&p_h, g_h);
    cudaGetSymbolAddress((void**)&p_hcn, g_hcn);
    cudaGetSymbolAddress((void**)&p_bc1, g_bc1);
    cudaGetSymbolAddress((void**)&p_bc2, g_bc2);
    cudaGetSymbolAddress((void**)&p_x1h, g_x1h);
    cudaGetSymbolAddress((void**)&p_x2h, g_x2h);
    cudaGetSymbolAddress((void**)&p_W1h, g_Wt1h);
    cudaGetSymbolAddress((void**)&p_W1l, g_Wt1l);
    cudaGetSymbolAddress((void**)&p_W2h, g_Wt2h);
    cudaGetSymbolAddress((void**)&p_W2l, g_Wt2l);

    cudaFuncSetAttribute(mma_gemm, cudaFuncAttributeMaxDynamicSharedMemorySize, MG_SMEM);
    cudaFuncSetAttribute(edge1_mma, cudaFuncAttributeMaxDynamicSharedMemorySize, E_SMEM);

    setup_weights<<<704, 256>>>(m1W1, m1b1, m2W1, m2b1, m1W2);
    setup_wall<<<(B + 3) / 4, 256>>>(wall, w1, wb1, w2, wb2, B);
    node_kernel<<<(N + 31) / 32, 256>>>(t, obj_x, obj_geo, category,
                                        batch_idx, embed_W, gfp_W, sW, sb, i1, ib1, N);
    gemm128<<<(N + 127) / 128, 256>>>(p_h, i2, ib2, N);
    {
        dim3 g((N + 127) / 128, 2);
        mma_gemm<<<g, 256, MG_SMEM>>>(p_x1h, p_W1h, p_W1l, p_bc1, p_hcn, N);
    }
    edge1_mma<<<148, 384, E_SMEM>>>(src, m1b2, N, nt12);
    {
        dim3 g((N + 127) / 128, 2);
        mma_gemm<<<g, 256, MG_SMEM>>>(p_x2h, p_W2h, p_W2l, p_bc2, p_hcn, N);
    }
    edge2_kernel<<<(N + 7) / 8, 256>>>(src, m2W2, m2b2, (float*)d_out, N, EPN);
}

// round 14
// speedup vs baseline: 1.5409x; 1.1393x over previous
#include <cuda_runtime.h>
#include <cuda_fp16.h>
#include <math.h>
#include <float.h>
#include <stdint.h>

#define NMAX 50000
#define BMAX 1024

__device__ float g_wall_h[BMAX * 64];
__device__ float g_h[NMAX * 128];
__device__ float g_hcn[NMAX * 256];
__device__ float g_sinv[NMAX];
__device__ __align__(16) __half g_x1h[NMAX * 320];
__device__ __align__(16) __half g_x2h[NMAX * 320];
__device__ __align__(16) __half g_Wt1h[256 * 320];
__device__ __align__(16) __half g_Wt2h[256 * 320];
__device__ __align__(16) __half g_W2th[128 * 128];
__device__ float g_bc1[256];
__device__ float g_bc2[256];

// ---- helpers ----
__device__ __forceinline__ uint32_t smem_u32(const void* p) {
    uint32_t a;
    asm("{ .reg .u64 t; cvta.to.shared.u64 t, %1; cvt.u32.u64 %0, t; }" : "=r"(a) : "l"(p));
    return a;
}
__device__ __forceinline__ void ldsm_x4(uint32_t* r, uint32_t addr) {
    asm volatile("ldmatrix.sync.aligned.m8n8.x4.shared.b16 {%0,%1,%2,%3}, [%4];"
                 : "=r"(r[0]), "=r"(r[1]), "=r"(r[2]), "=r"(r[3]) : "r"(addr));
}
__device__ __forceinline__ void mma_f16(float* c, const uint32_t* a, const uint32_t* b) {
    asm volatile("mma.sync.aligned.m16n8k16.row.col.f32.f16.f16.f32 "
                 "{%0,%1,%2,%3}, {%4,%5,%6,%7}, {%8,%9}, {%0,%1,%2,%3};"
                 : "+f"(c[0]), "+f"(c[1]), "+f"(c[2]), "+f"(c[3])
                 : "r"(a[0]), "r"(a[1]), "r"(a[2]), "r"(a[3]), "r"(b[0]), "r"(b[1]));
}
#define CP_ASYNC(dst, src) \
    asm volatile("cp.async.cg.shared.global [%0], [%1], 16;" :: "r"(dst), "l"(src) : "memory")
#define CP_COMMIT() asm volatile("cp.async.commit_group;" ::: "memory")
#define CP_WAIT(n)  asm volatile("cp.async.wait_group %0;" :: "n"(n) : "memory")

__device__ __forceinline__ uint32_t packh2(float a, float b) {
    __half2 p = __floats2half2_rn(a, b);
    return *reinterpret_cast<uint32_t*>(&p);
}
__device__ __forceinline__ unsigned long long dup2(float x) {
    unsigned long long r; asm("mov.b64 %0, {%1, %1};" : "=l"(r) : "f"(x)); return r;
}
__device__ __forceinline__ void ffma2(unsigned long long& d, unsigned long long a, unsigned long long b) {
    asm("fma.rn.f32x2 %0, %1, %2, %0;" : "+l"(d) : "l"(a), "l"(b));
}
__device__ __forceinline__ float2 unpack2(unsigned long long p) {
    float lo, hi; asm("mov.b64 {%0, %1}, %2;" : "=f"(lo), "=f"(hi) : "l"(p)); return make_float2(lo, hi);
}

// ---------------------------------------------------------------------------
__global__ void __launch_bounds__(256) setup_weights(
    const float* __restrict__ m1W1, const float* __restrict__ m1b1,
    const float* __restrict__ m2W1, const float* __restrict__ m2b1,
    const float* __restrict__ m1W2) {
    int b = blockIdx.x, tid = threadIdx.x;
    if (b < 640) {
        int sel = b >= 320;
        const float* W1 = sel ? m2W1 : m1W1;
        const float* b1 = sel ? m2b1 : m1b1;
        __half* Wh = sel ? g_Wt2h : g_Wt1h;
        float* bc = sel ? g_bc2 : g_bc1;
        int idx = (sel ? b - 320 : b) * 256 + tid;
        if (idx < 256 * 320) {
            int c = idx / 320, k = idx - c * 320;
            float v = (c < 128) ? (W1[k*128+c] - W1[(k+320)*128+c]) : W1[(k+320)*128+(c-128)];
            Wh[idx] = __float2half_rn(v);
        }
        if (idx < 256) bc[idx] = (idx < 128) ? b1[idx] : 0.f;
    } else {
        int idx = (b - 640) * 256 + tid;
        int c = idx >> 7, k = idx & 127;
        g_W2th[idx] = __float2half_rn(m1W2[k*128+c]);
    }
}

__global__ void __launch_bounds__(256) setup_wall(
    const float* __restrict__ wall, const float* __restrict__ w1,
    const float* __restrict__ wb1, const float* __restrict__ w2,
    const float* __restrict__ wb2, int B) {
    __shared__ float h[4][64];
    int tid = threadIdx.x;
    int row = blockIdx.x * 4 + (tid >> 6), k = tid & 63, rr = tid >> 6;
    if (row < B)
        h[rr][k] = fmaxf(wall[row*2]*w1[k] + wall[row*2+1]*w1[64+k] + wb1[k], 0.f);
    __syncthreads();
    if (row < B) {
        float acc = wb2[k];
#pragma unroll 8
        for (int i = 0; i < 64; i++) acc += h[rr][i] * w2[i*64+k];
        g_wall_h[row*64+k] = fmaxf(acc, 0.f);
    }
}

// ---------------------------------------------------------------------------
__global__ void __launch_bounds__(256) node_kernel(
    const float* __restrict__ t, const float* __restrict__ obj_x, const float* __restrict__ obj_geo,
    const int* __restrict__ category, const int* __restrict__ batch_idx,
    const float* __restrict__ embed_W, const float* __restrict__ gfp_W,
    const float* __restrict__ sW, const float* __restrict__ sb,
    const float* __restrict__ i1, const float* __restrict__ ib1, int N) {
    __shared__ float sWsh[64*64], i1sh[6*128], embsh[10*64], gfpsh[32], ib1sh[128], sbsh[64];
    __shared__ float2 gd[8][64];
    int tid = threadIdx.x, warp = tid >> 5, lane = tid & 31;
    for (int i = tid; i < 4096; i += 256) sWsh[i] = sW[i];
    for (int i = tid; i < 768; i += 256) i1sh[i] = i1[i];
    for (int i = tid; i < 640; i += 256) embsh[i] = embed_W[i];
    if (tid < 32) gfpsh[tid] = gfp_W[tid];
    if (tid < 128) ib1sh[tid] = ib1[tid];
    if (tid < 64) sbsh[tid] = sb[tid];
    __syncthreads();
    int base = blockIdx.x * 32;
#pragma unroll
    for (int it = 0; it < 4; it++) {
        int n = base + it * 8 + warp;
        if (n >= N) continue;
        float tv = __ldg(t + n);
        float p = tv * gfpsh[lane] * 6.283185307179586f;
        float sv = sinf(p), cv = cosf(p);
        gd[warp][lane] = make_float2(sv, sv);
        gd[warp][lane+32] = make_float2(cv, cv);
        int cat = category[n], bi = batch_idx[n];
        uint32_t* x1hu = reinterpret_cast<uint32_t*>(g_x1h);
        size_t nb = (size_t)n * 160;
        x1hu[nb + 64 + lane] = packh2(fmaxf(embsh[cat*64 + 2*lane], 0.f),
                                      fmaxf(embsh[cat*64 + 2*lane + 1], 0.f));
        x1hu[nb + 128 + lane] = packh2(g_wall_h[bi*64 + 2*lane], g_wall_h[bi*64 + 2*lane + 1]);
        if (lane == 0) {
            const float LN25 = 3.2188758248682006f;
            float stdv = sqrtf((expf(2.f*tv*LN25) - 1.f) / (2.f*LN25));
            g_sinv[n] = 1.f / (stdv + 1e-7f);
        }
        float xv = 0.f;
        if (lane < 4) xv = obj_x[n*4+lane]; else if (lane < 6) xv = obj_geo[n*2+lane-4];
        float4 a = *reinterpret_cast<const float4*>(ib1sh + lane*4);
#pragma unroll
        for (int i = 0; i < 6; i++) {
            float xi = __shfl_sync(0xffffffffu, xv, i);
            float4 w = *reinterpret_cast<const float4*>(i1sh + i*128 + lane*4);
            a.x += xi*w.x; a.y += xi*w.y; a.z += xi*w.z; a.w += xi*w.w;
        }
        a.x = fmaxf(a.x,0.f); a.y = fmaxf(a.y,0.f); a.z = fmaxf(a.z,0.f); a.w = fmaxf(a.w,0.f);
        *reinterpret_cast<float4*>(g_h + (size_t)n*128 + lane*4) = a;
        __syncwarp();
        unsigned long long accp = *reinterpret_cast<const unsigned long long*>(sbsh + lane*2);
#pragma unroll 8
        for (int i = 0; i < 64; i++)
            ffma2(accp, *reinterpret_cast<const unsigned long long*>(&gd[warp][i]),
                  *reinterpret_cast<const unsigned long long*>(sWsh + i*64 + lane*2));
        float2 v = unpack2(accp);
        x1hu[nb + 96 + lane] = packh2(fmaxf(v.x,0.f), fmaxf(v.y,0.f));
        __syncwarp();
    }
}

// ---------------------------------------------------------------------------
__global__ void __launch_bounds__(256, 2) gemm128(
    const float* __restrict__ A, const float* __restrict__ W,
    const float* __restrict__ bias, int N) {
    __shared__ float At[16][132], Ws[16][128];
    int tid = threadIdx.x, rowBase = blockIdx.x * 128;
    int rg = tid >> 4, cg = tid & 15;
    unsigned long long acc[8][4];
#pragma unroll
    for (int r = 0; r < 8; r++) for (int c = 0; c < 4; c++) acc[r][c] = 0ULL;
    for (int kc = 0; kc < 128; kc += 16) {
        __syncthreads();
#pragma unroll
        for (int i = 0; i < 2; i++) {
            int idx = tid + i*256, r = idx >> 2, kq = (idx & 3) << 2;
            int row = rowBase + r; if (row > N-1) row = N-1;
            float4 v = *reinterpret_cast<const float4*>(A + (size_t)row*128 + kc + kq);
            At[kq][r] = v.x; At[kq+1][r] = v.y; At[kq+2][r] = v.z; At[kq+3][r] = v.w;
        }
#pragma unroll
        for (int i = 0; i < 2; i++) {
            int idx = tid + i*256, k = idx >> 5, c4 = (idx & 31) << 2;
            *reinterpret_cast<float4*>(&Ws[k][c4]) =
                *reinterpret_cast<const float4*>(W + (size_t)(kc+k)*128 + c4);
        }
        __syncthreads();
#pragma unroll
        for (int kk = 0; kk < 16; kk++) {
            float4 a0 = *reinterpret_cast<const float4*>(&At[kk][rg*8]);
            float4 a1 = *reinterpret_cast<const float4*>(&At[kk][rg*8+4]);
            ulonglong2 w0 = *reinterpret_cast<const ulonglong2*>(&Ws[kk][cg*8]);
            ulonglong2 w1 = *reinterpret_cast<const ulonglong2*>(&Ws[kk][cg*8+4]);
            unsigned long long ad[8] = {dup2(a0.x),dup2(a0.y),dup2(a0.z),dup2(a0.w),
                                        dup2(a1.x),dup2(a1.y),dup2(a1.z),dup2(a1.w)};
#pragma unroll
            for (int r = 0; r < 8; r++) {
                ffma2(acc[r][0], ad[r], w0.x); ffma2(acc[r][1], ad[r], w0.y);
                ffma2(acc[r][2], ad[r], w1.x); ffma2(acc[r][3], ad[r], w1.y);
            }
        }
    }
    float4 b0 = *reinterpret_cast<const float4*>(bias + cg*8);
    float4 b1 = *reinterpret_cast<const float4*>(bias + cg*8 + 4);
    uint32_t* x1hu = reinterpret_cast<uint32_t*>(g_x1h);
#pragma unroll
    for (int r = 0; r < 8; r++) {
        int row = rowBase + rg*8 + r;
        if (row < N) {
            float2 v0 = unpack2(acc[r][0]), v1 = unpack2(acc[r][1]);
            float2 v2 = unpack2(acc[r][2]), v3 = unpack2(acc[r][3]);
            uint32_t hh[4] = {
                packh2(fmaxf(v0.x+b0.x,0.f), fmaxf(v0.y+b0.y,0.f)),
                packh2(fmaxf(v1.x+b0.z,0.f), fmaxf(v1.y+b0.w,0.f)),
                packh2(fmaxf(v2.x+b1.x,0.f), fmaxf(v2.y+b1.y,0.f)),
                packh2(fmaxf(v3.x+b1.z,0.f), fmaxf(v3.y+b1.w,0.f))};
            size_t u = (size_t)row * 160 + cg * 4;
            *reinterpret_cast<uint2*>(x1hu + u)     = make_uint2(hh[0], hh[1]);
            *reinterpret_cast<uint2*>(x1hu + u + 2) = make_uint2(hh[2], hh[3]);
        }
    }
}

// ---------------------------------------------------------------------------
// mma.sync GEMM pure fp16 1-term. cp.async double buffered.
// smem per buf 20480B: [A 10240 | B 10240], pitch 40 halfs.
// ---------------------------------------------------------------------------
#define MG_SMEM 40960
__global__ void __launch_bounds__(256, 2) mma_gemm(
    const __half* __restrict__ Ah, const __half* __restrict__ Bh,
    const float* __restrict__ bias, float* __restrict__ out, int N) {
    extern __shared__ char sm[];
    uint32_t smb = smem_u32(sm);
    int tid = threadIdx.x, lane = tid & 31, warp = tid >> 5;
    int wm = warp & 3, wn = warp >> 2;
    int rowBase = blockIdx.x * 128, colBase = blockIdx.y * 128;
    float acc[2][8][4];
#pragma unroll
    for (int m = 0; m < 2; m++) for (int n = 0; n < 8; n++)
        for (int q = 0; q < 4; q++) acc[m][n][q] = 0.f;
    int aRow = lane & 15, aK = (lane >> 4) * 8;
    int bN = ((lane >> 4) << 3) + (lane & 7), bK = ((lane >> 3) & 1) * 8;
    int r0i = tid >> 2, q0 = (tid & 3);
    int r1i = (tid + 256) >> 2, q1 = ((tid + 256) & 3);

#define MG_STAGE(kc, buf) do {                                                     \
    uint32_t bb = smb + (buf) * 20480;                                             \
    int rows[2] = {r0i, r1i}; int qs[2] = {q0, q1};                                \
    _Pragma("unroll")                                                              \
    for (int m = 0; m < 2; m++) {                                                  \
        int r = rows[m], q = qs[m];                                                \
        int row = rowBase + r; if (row > N-1) row = N-1;                           \
        uint32_t da = bb + r*80 + q*16;                                            \
        CP_ASYNC(da, Ah + (size_t)row*320 + (kc)*32 + q*8);                        \
        CP_ASYNC(da + 10240, Bh + (size_t)(colBase + r)*320 + (kc)*32 + q*8);      \
    } } while (0)

    MG_STAGE(0, 0);
    CP_COMMIT();
    for (int kc = 0; kc < 10; kc++) {
        int buf = kc & 1;
        if (kc < 9) { MG_STAGE(kc + 1, buf ^ 1); CP_COMMIT(); CP_WAIT(1); }
        else CP_WAIT(0);
        __syncthreads();
        uint32_t bb = smb + buf * 20480;
#pragma unroll
        for (int ks = 0; ks < 32; ks += 16) {
            uint32_t ah[2][4], bh[4][4];
#pragma unroll
            for (int mt = 0; mt < 2; mt++)
                ldsm_x4(ah[mt], bb + ((wm*32 + mt*16 + aRow) * 40 + ks + aK) * 2);
#pragma unroll
            for (int bt = 0; bt < 4; bt++)
                ldsm_x4(bh[bt], bb + 10240 + ((wn*64 + bt*16 + bN) * 40 + ks + bK) * 2);
#pragma unroll
            for (int mt = 0; mt < 2; mt++)
#pragma unroll
                for (int nt = 0; nt < 8; nt++)
                    mma_f16(acc[mt][nt], ah[mt], &bh[nt>>1][(nt&1)*2]);
        }
        __syncthreads();
    }
    int g = lane >> 2, tq = (lane & 3) * 2;
#pragma unroll
    for (int mt = 0; mt < 2; mt++) {
        int r0 = rowBase + wm*32 + mt*16 + g;
#pragma unroll
        for (int nt = 0; nt < 8; nt++) {
            int c0 = colBase + wn*64 + nt*8 + tq;
            float b0 = __ldg(bias + c0), b1 = __ldg(bias + c0 + 1);
            if (r0 < N) {
                out[(size_t)r0*256 + c0]     = acc[mt][nt][0] + b0;
                out[(size_t)r0*256 + c0 + 1] = acc[mt][nt][1] + b1;
            }
            if (r0 + 8 < N) {
                out[(size_t)(r0+8)*256 + c0]     = acc[mt][nt][2] + b0;
                out[(size_t)(r0+8)*256 + c0 + 1] = acc[mt][nt][3] + b1;
            }
        }
    }
}

// ---------------------------------------------------------------------------
// Edge conv1 pure fp16: 384 threads, warps 0-7 mma (2/SMSP), 8-11 builders.
// smem: W2h @0 | R0 @34816 | R1 @69632 (each 34816B, pitch 136 halfs).
// ---------------------------------------------------------------------------
#define EP 136
#define E_SMEM 104448

__device__ __forceinline__ void edge1_build(char* sm, int roff, int tile,
                                            const int* __restrict__ src, int N, int tid2) {
    int r = tid2;
    int local = r & 31;
    int s = local / 10, j = local - s * 10;
    int n = tile * 12 + (r >> 5) * 3 + s;
    if (local < 30 && n < N) {
        int sidx = src[n + j * N];
        const float4* hc4 = reinterpret_cast<const float4*>(g_hcn + (size_t)n * 256);
        const float4* hn4 = reinterpret_cast<const float4*>(g_hcn + (size_t)sidx * 256 + 128);
        char* bh = sm + roff + r * (EP * 2);
#pragma unroll 4
        for (int i = 0; i < 32; i++) {
            float4 a = hc4[i], b = hn4[i];
            *reinterpret_cast<uint2*>(bh + i * 8) = make_uint2(
                packh2(fmaxf(a.x + b.x, 0.f), fmaxf(a.y + b.y, 0.f)),
                packh2(fmaxf(a.z + b.z, 0.f), fmaxf(a.w + b.w, 0.f)));
        }
    }
    for (int q = tid2; q < 1152; q += 128) {
        int ln = q / 96, o = q - ln * 96, n2 = tile * 12 + ln;
        if (n2 < N) {
            size_t u = (size_t)n2 * 160 + 64 + o;
            reinterpret_cast<uint32_t*>(g_x2h)[u] = reinterpret_cast<const uint32_t*>(g_x1h)[u];
        }
    }
}

__global__ void __launch_bounds__(384, 1) edge1_mma(
    const int* __restrict__ src, const float* __restrict__ b2, int N, int ntiles) {
    extern __shared__ char sm[];
    __shared__ float b2s[128];
    int tid = threadIdx.x, lane = tid & 31, warp = tid >> 5;
    if (tid < 128) b2s[tid] = b2[tid];
    // W2 preload: 128 rows x 16 chunks of 8 halfs
    for (int idx = tid; idx < 2048; idx += 384) {
        int r = idx >> 4, kq = (idx & 15) * 8;
        *reinterpret_cast<uint4*>(sm + (r*EP + kq)*2) =
            *reinterpret_cast<const uint4*>(g_W2th + r*128 + kq);
    }
    // zero unused R rows (local 30,31 of each 32-row group), both buffers
    for (int idx = tid; idx < 1088; idx += 384) {
        int rowsel = idx / 68, u = idx - rowsel * 68;
        int buf = rowsel >> 3, ri = rowsel & 7;
        int row = (ri >> 1) * 32 + 30 + (ri & 1);
        *reinterpret_cast<uint32_t*>(sm + 34816 + buf*34816 + row*(EP*2) + u*4) = 0u;
    }
    if (warp >= 8 && (int)blockIdx.x < ntiles)
        edge1_build(sm, 34816, blockIdx.x, src, N, tid - 256);
    __syncthreads();

    uint32_t smb = smem_u32(sm);
    uint32_t uW2h = smb;
    int aRow = lane & 15, aK = (lane >> 4) * 8;
    int bN_ = ((lane >> 4) << 3) + (lane & 7), bK = ((lane >> 3) & 1) * 8;
    int g = lane >> 2;
    int wm = warp & 3, wn = (warp >> 2) & 1;

    int lt = 0;
    for (int tile = blockIdx.x; tile < ntiles; tile += gridDim.x, lt ^= 1) {
        int roff = 34816 + lt * 34816;
        if (warp < 8) {
            uint32_t uR = smb + roff;
            float acc[2][8][4];
#pragma unroll
            for (int m = 0; m < 2; m++)
#pragma unroll
                for (int n = 0; n < 8; n++)
#pragma unroll
                    for (int q = 0; q < 4; q++) acc[m][n][q] = 0.f;
#pragma unroll
            for (int ks = 0; ks < 128; ks += 16) {
                uint32_t ah[2][4], bh[4][4];
#pragma unroll
                for (int mt = 0; mt < 2; mt++)
                    ldsm_x4(ah[mt], uR + ((wm*32 + mt*16 + aRow) * EP + ks + aK) * 2);
#pragma unroll
                for (int bt = 0; bt < 4; bt++)
                    ldsm_x4(bh[bt], uW2h + ((wn*64 + bt*16 + bN_) * EP + ks + bK) * 2);
#pragma unroll
                for (int mt = 0; mt < 2; mt++)
#pragma unroll
                    for (int nt = 0; nt < 8; nt++)
                        mma_f16(acc[mt][nt], ah[mt], &bh[nt>>1][(nt&1)*2]);
            }
            int n0 = tile * 12 + wm * 3;
#pragma unroll
            for (int nt = 0; nt < 8; nt++) {
                float e0 = acc[0][nt][0], o0 = acc[0][nt][1];
                if (g < 2) { e0 = fmaxf(e0, acc[0][nt][2]); o0 = fmaxf(o0, acc[0][nt][3]); }
                float e1 = (g >= 2) ? acc[0][nt][2] : -FLT_MAX;
                float o1 = (g >= 2) ? acc[0][nt][3] : -FLT_MAX;
                if (g < 4) { e1 = fmaxf(e1, acc[1][nt][0]); o1 = fmaxf(o1, acc[1][nt][1]); }
                float e2 = (g >= 4) ? acc[1][nt][0] : -FLT_MAX;
                float o2 = (g >= 4) ? acc[1][nt][1] : -FLT_MAX;
                if (g < 6) { e2 = fmaxf(e2, acc[1][nt][2]); o2 = fmaxf(o2, acc[1][nt][3]); }
#pragma unroll
                for (int off = 4; off <= 16; off <<= 1) {
                    e0 = fmaxf(e0, __shfl_xor_sync(0xffffffffu, e0, off));
                    o0 = fmaxf(o0, __shfl_xor_sync(0xffffffffu, o0, off));
                    e1 = fmaxf(e1, __shfl_xor_sync(0xffffffffu, e1, off));
                    o1 = fmaxf(o1, __shfl_xor_sync(0xffffffffu, o1, off));
                    e2 = fmaxf(e2, __shfl_xor_sync(0xffffffffu, e2, off));
                    o2 = fmaxf(o2, __shfl_xor_sync(0xffffffffu, o2, off));
                }
                if (lane < 4) {
                    int colb = wn*64 + nt*8 + lane*2;
                    float bce = b2s[colb], bco = b2s[colb+1];
                    float ve[3] = {fmaxf(e0+bce,0.f), fmaxf(e1+bce,0.f), fmaxf(e2+bce,0.f)};
                    float vo[3] = {fmaxf(o0+bco,0.f), fmaxf(o1+bco,0.f), fmaxf(o2+bco,0.f)};
#pragma unroll
                    for (int s = 0; s < 3; s++) {
                        int n = n0 + s;
                        if (n < N)
                            reinterpret_cast<uint32_t*>(g_x2h)[(size_t)n * 160 + (colb >> 1)] =
                                packh2(ve[s], vo[s]);
                    }
                }
            }
        } else {
            int nxt = tile + gridDim.x;
            if (nxt < ntiles)
                edge1_build(sm, 34816 + (lt ^ 1) * 34816, nxt, src, N, tid - 256);
        }
        __syncthreads();
    }
}

// ---------------------------------------------------------------------------
__global__ void edge2_kernel(const int* __restrict__ src, const float* __restrict__ W2s,
                             const float* __restrict__ b2, float* __restrict__ out,
                             int N, int EPN) {
    int gw = (blockIdx.x * blockDim.x + threadIdx.x) >> 5;
    int lane = threadIdx.x & 31;
    if (gw >= N) return;
    int n = gw;
    int b0 = lane & 1, b1 = (lane >> 1) & 1;
    int c = 2*b0 + b1;
    float4 wr0 = *reinterpret_cast<const float4*>(W2s + (lane*4)*4);
    float4 wr1 = *reinterpret_cast<const float4*>(W2s + (lane*4+1)*4);
    float4 wr2 = *reinterpret_cast<const float4*>(W2s + (lane*4+2)*4);
    float4 wr3 = *reinterpret_cast<const float4*>(W2s + (lane*4+3)*4);
    float bc = __ldg(b2 + c);
    float4 hc = *reinterpret_cast<const float4*>(&g_hcn[(size_t)n*256 + lane*4]);
    float mx = -FLT_MAX;
#pragma unroll
    for (int j = 0; j < 10; j++) {
        int s = src[n + j*N];
        float4 hb = *reinterpret_cast<const float4*>(&g_hcn[(size_t)s*256 + 128 + lane*4]);
        float r0 = fmaxf(hc.x+hb.x,0.f), r1 = fmaxf(hc.y+hb.y,0.f);
        float r2 = fmaxf(hc.z+hb.z,0.f), r3 = fmaxf(hc.w+hb.w,0.f);
        float y0 = r0*wr0.x + r1*wr1.x + r2*wr2.x + r3*wr3.x;
        float y1 = r0*wr0.y + r1*wr1.y + r2*wr2.y + r3*wr3.y;
        float y2 = r0*wr0.z + r1*wr1.z + r2*wr2.z + r3*wr3.z;
        float y3 = r0*wr0.w + r1*wr1.w + r2*wr2.w + r3*wr3.w;
        float t0 = __shfl_xor_sync(0xffffffffu, b0 ? y0 : y2, 1);
        float t1 = __shfl_xor_sync(0xffffffffu, b0 ? y1 : y3, 1);
        float p0 = (b0 ? y2 : y0) + t0;
        float p1 = (b0 ? y3 : y1) + t1;
        float t2 = __shfl_xor_sync(0xffffffffu, b1 ? p0 : p1, 2);
        float z  = (b1 ? p1 : p0) + t2;
        z += __shfl_xor_sync(0xffffffffu, z, 4);
        z += __shfl_xor_sync(0xffffffffu, z, 8);
        z += __shfl_xor_sync(0xffffffffu, z, 16);
        mx = fmaxf(mx, z);
    }
    if (lane < 4) out[(size_t)n*4 + c] = (mx + bc) * g_sinv[n];
}

// ---------------------------------------------------------------------------
extern "C" void kernel_launch(void* const* d_in, const int* in_sizes, int n_in,
                              void* d_out, int out_size) {
    const float* t        = (const float*)d_in[0];
    const float* obj_x    = (const float*)d_in[1];
    const float* obj_geo  = (const float*)d_in[2];
    const float* wall     = (const float*)d_in[3];
    const int*   category = (const int*)d_in[4];
    const int*   batch_idx= (const int*)d_in[5];
    const int*   src      = (const int*)d_in[6];
    const float* embed_W  = (const float*)d_in[8];
    const float* gfp_W    = (const float*)d_in[9];
    const float* sW       = (const float*)d_in[10];
    const float* sb       = (const float*)d_in[11];
    const float* w1       = (const float*)d_in[12];
    const float* wb1      = (const float*)d_in[13];
    const float* w2       = (const float*)d_in[14];
    const float* wb2      = (const float*)d_in[15];
    const float* i1       = (const float*)d_in[16];
    const float* ib1      = (const float*)d_in[17];
    const float* i2       = (const float*)d_in[18];
    const float* ib2      = (const float*)d_in[19];
    const float* m1W1     = (const float*)d_in[20];
    const float* m1b1     = (const float*)d_in[21];
    const float* m1W2     = (const float*)d_in[22];
    const float* m1b2     = (const float*)d_in[23];
    const float* m2W1     = (const float*)d_in[24];
    const float* m2b1     = (const float*)d_in[25];
    const float* m2W2     = (const float*)d_in[26];
    const float* m2b2     = (const float*)d_in[27];

    int N = in_sizes[0], E = in_sizes[6], B = in_sizes[3] / 2;
    int EPN = E / N;
    int nt12 = (N + 11) / 12;

    float *p_h, *p_hcn, *p_bc1, *p_bc2;
    __half *p_x1h, *p_x2h, *p_W1h, *p_W2h;
    cudaGetSymbolAddress((void**)&p_h, g_h);
    cudaGetSymbolAddress((void**)&p_hcn, g_hcn);
    cudaGetSymbolAddress((void**)&p_bc1, g_bc1);
    cudaGetSymbolAddress((void**)&p_bc2, g_bc2);
    cudaGetSymbolAddress((void**)&p_x1h, g_x1h);
    cudaGetSymbolAddress((void**)&p_x2h, g_x2h);
    cudaGetSymbolAddress((void**)&p_W1h, g_Wt1h);
    cudaGetSymbolAddress((void**)&p_W2h, g_Wt2h);

    cudaFuncSetAttribute(mma_gemm, cudaFuncAttributeMaxDynamicSharedMemorySize, MG_SMEM);
    cudaFuncSetAttribute(edge1_mma, cudaFuncAttributeMaxDynamicSharedMemorySize, E_SMEM);

    setup_weights<<<704, 256>>>(m1W1, m1b1, m2W1, m2b1, m1W2);
    setup_wall<<<(B + 3) / 4, 256>>>(wall, w1, wb1, w2, wb2, B);
    node_kernel<<<(N + 31) / 32, 256>>>(t, obj_x, obj_geo, category,
                                        batch_idx, embed_W, gfp_W, sW, sb, i1, ib1, N);
    gemm128<<<(N + 127) / 128, 256>>>(p_h, i2, ib2, N);
    {
        dim3 g((N + 127) / 128, 2);
        mma_gemm<<<g, 256, MG_SMEM>>>(p_x1h, p_W1h, p_bc1, p_hcn, N);
    }
    edge1_mma<<<148, 384, E_SMEM>>>(src, m1b2, N, nt12);
    {
        dim3 g((N + 127) / 128, 2);
        mma_gemm<<<g, 256, MG_SMEM>>>(p_x2h, p_W2h, p_bc2, p_hcn, N);
    }
    edge2_kernel<<<(N + 7) / 8, 256>>>(src, m2W2, m2b2, (float*)d_out, N, EPN);
}

// round 15
// speedup vs baseline: 2.1641x; 1.4045x over previous
#include <cuda_runtime.h>
#include <cuda_fp16.h>
#include <math.h>
#include <float.h>
#include <stdint.h>

#define NMAX 50000
#define BMAX 1024

__device__ float g_wall_h[BMAX * 64];
__device__ __align__(16) __half g_h[NMAX * 128];
__device__ __align__(16) __half g_hcn[NMAX * 256];   // fp16 [hc'(128) | hn(128)]
__device__ float g_sinv[NMAX];
__device__ __align__(16) __half g_x1h[NMAX * 320];
__device__ __align__(16) __half g_x2h[NMAX * 320];
__device__ __align__(16) __half g_Wt1h[256 * 320];
__device__ __align__(16) __half g_Wt2h[256 * 320];
__device__ __align__(16) __half g_W2th[128 * 128];
__device__ __align__(16) __half g_i2t[128 * 128];
__device__ float g_bc1[256];
__device__ float g_bc2[256];

// ---- helpers ----
__device__ __forceinline__ uint32_t smem_u32(const void* p) {
    uint32_t a;
    asm("{ .reg .u64 t; cvta.to.shared.u64 t, %1; cvt.u32.u64 %0, t; }" : "=r"(a) : "l"(p));
    return a;
}
__device__ __forceinline__ void ldsm_x4(uint32_t* r, uint32_t addr) {
    asm volatile("ldmatrix.sync.aligned.m8n8.x4.shared.b16 {%0,%1,%2,%3}, [%4];"
                 : "=r"(r[0]), "=r"(r[1]), "=r"(r[2]), "=r"(r[3]) : "r"(addr));
}
__device__ __forceinline__ void mma_f16(float* c, const uint32_t* a, const uint32_t* b) {
    asm volatile("mma.sync.aligned.m16n8k16.row.col.f32.f16.f16.f32 "
                 "{%0,%1,%2,%3}, {%4,%5,%6,%7}, {%8,%9}, {%0,%1,%2,%3};"
                 : "+f"(c[0]), "+f"(c[1]), "+f"(c[2]), "+f"(c[3])
                 : "r"(a[0]), "r"(a[1]), "r"(a[2]), "r"(a[3]), "r"(b[0]), "r"(b[1]));
}
#define CP_ASYNC(dst, src) \
    asm volatile("cp.async.cg.shared.global [%0], [%1], 16;" :: "r"(dst), "l"(src) : "memory")
#define CP_COMMIT() asm volatile("cp.async.commit_group;" ::: "memory")
#define CP_WAIT(n)  asm volatile("cp.async.wait_group %0;" :: "n"(n) : "memory")

__device__ __forceinline__ uint32_t packh2(float a, float b) {
    __half2 p = __floats2half2_rn(a, b);
    return *reinterpret_cast<uint32_t*>(&p);
}
__device__ __forceinline__ unsigned long long dup2(float x) {
    unsigned long long r; asm("mov.b64 %0, {%1, %1};" : "=l"(r) : "f"(x)); return r;
}
__device__ __forceinline__ void ffma2(unsigned long long& d, unsigned long long a, unsigned long long b) {
    asm("fma.rn.f32x2 %0, %1, %2, %0;" : "+l"(d) : "l"(a), "l"(b));
}
__device__ __forceinline__ float2 unpack2(unsigned long long p) {
    float lo, hi; asm("mov.b64 {%0, %1}, %2;" : "=f"(lo), "=f"(hi) : "l"(p)); return make_float2(lo, hi);
}

// ---------------------------------------------------------------------------
__global__ void __launch_bounds__(256) setup_weights(
    const float* __restrict__ m1W1, const float* __restrict__ m1b1,
    const float* __restrict__ m2W1, const float* __restrict__ m2b1,
    const float* __restrict__ m1W2, const float* __restrict__ i2) {
    int b = blockIdx.x, tid = threadIdx.x;
    if (b < 640) {
        int sel = b >= 320;
        const float* W1 = sel ? m2W1 : m1W1;
        const float* b1 = sel ? m2b1 : m1b1;
        __half* Wh = sel ? g_Wt2h : g_Wt1h;
        float* bc = sel ? g_bc2 : g_bc1;
        int idx = (sel ? b - 320 : b) * 256 + tid;
        if (idx < 256 * 320) {
            int c = idx / 320, k = idx - c * 320;
            float v = (c < 128) ? (W1[k*128+c] - W1[(k+320)*128+c]) : W1[(k+320)*128+(c-128)];
            Wh[idx] = __float2half_rn(v);
        }
        if (idx < 256) bc[idx] = (idx < 128) ? b1[idx] : 0.f;
    } else if (b < 704) {
        int idx = (b - 640) * 256 + tid;
        int c = idx >> 7, k = idx & 127;
        g_W2th[idx] = __float2half_rn(m1W2[k*128+c]);
    } else {
        int idx = (b - 704) * 256 + tid;
        int c = idx >> 7, k = idx & 127;
        g_i2t[idx] = __float2half_rn(i2[k*128+c]);
    }
}

__global__ void __launch_bounds__(256) setup_wall(
    const float* __restrict__ wall, const float* __restrict__ w1,
    const float* __restrict__ wb1, const float* __restrict__ w2,
    const float* __restrict__ wb2, int B) {
    __shared__ float h[4][64];
    int tid = threadIdx.x;
    int row = blockIdx.x * 4 + (tid >> 6), k = tid & 63, rr = tid >> 6;
    if (row < B)
        h[rr][k] = fmaxf(wall[row*2]*w1[k] + wall[row*2+1]*w1[64+k] + wb1[k], 0.f);
    __syncthreads();
    if (row < B) {
        float acc = wb2[k];
#pragma unroll 8
        for (int i = 0; i < 64; i++) acc += h[rr][i] * w2[i*64+k];
        g_wall_h[row*64+k] = fmaxf(acc, 0.f);
    }
}

// ---------------------------------------------------------------------------
__global__ void __launch_bounds__(256) node_kernel(
    const float* __restrict__ t, const float* __restrict__ obj_x, const float* __restrict__ obj_geo,
    const int* __restrict__ category, const int* __restrict__ batch_idx,
    const float* __restrict__ embed_W, const float* __restrict__ gfp_W,
    const float* __restrict__ sW, const float* __restrict__ sb,
    const float* __restrict__ i1, const float* __restrict__ ib1, int N) {
    __shared__ float sWsh[64*64], i1sh[6*128], embsh[10*64], gfpsh[32], ib1sh[128], sbsh[64];
    __shared__ float2 gd[8][64];
    int tid = threadIdx.x, warp = tid >> 5, lane = tid & 31;
    for (int i = tid; i < 4096; i += 256) sWsh[i] = sW[i];
    for (int i = tid; i < 768; i += 256) i1sh[i] = i1[i];
    for (int i = tid; i < 640; i += 256) embsh[i] = embed_W[i];
    if (tid < 32) gfpsh[tid] = gfp_W[tid];
    if (tid < 128) ib1sh[tid] = ib1[tid];
    if (tid < 64) sbsh[tid] = sb[tid];
    __syncthreads();
    int base = blockIdx.x * 32;
#pragma unroll
    for (int it = 0; it < 4; it++) {
        int n = base + it * 8 + warp;
        if (n >= N) continue;
        float tv = __ldg(t + n);
        float p = tv * gfpsh[lane] * 6.283185307179586f;
        float sv = sinf(p), cv = cosf(p);
        gd[warp][lane] = make_float2(sv, sv);
        gd[warp][lane+32] = make_float2(cv, cv);
        int cat = category[n], bi = batch_idx[n];
        uint32_t* x1hu = reinterpret_cast<uint32_t*>(g_x1h);
        size_t nb = (size_t)n * 160;
        x1hu[nb + 64 + lane] = packh2(fmaxf(embsh[cat*64 + 2*lane], 0.f),
                                      fmaxf(embsh[cat*64 + 2*lane + 1], 0.f));
        x1hu[nb + 128 + lane] = packh2(g_wall_h[bi*64 + 2*lane], g_wall_h[bi*64 + 2*lane + 1]);
        if (lane == 0) {
            const float LN25 = 3.2188758248682006f;
            float stdv = sqrtf((expf(2.f*tv*LN25) - 1.f) / (2.f*LN25));
            g_sinv[n] = 1.f / (stdv + 1e-7f);
        }
        float xv = 0.f;
        if (lane < 4) xv = obj_x[n*4+lane]; else if (lane < 6) xv = obj_geo[n*2+lane-4];
        float4 a = *reinterpret_cast<const float4*>(ib1sh + lane*4);
#pragma unroll
        for (int i = 0; i < 6; i++) {
            float xi = __shfl_sync(0xffffffffu, xv, i);
            float4 w = *reinterpret_cast<const float4*>(i1sh + i*128 + lane*4);
            a.x += xi*w.x; a.y += xi*w.y; a.z += xi*w.z; a.w += xi*w.w;
        }
        *reinterpret_cast<uint2*>(reinterpret_cast<uint32_t*>(g_h) + (size_t)n*64 + lane*2) =
            make_uint2(packh2(fmaxf(a.x,0.f), fmaxf(a.y,0.f)),
                       packh2(fmaxf(a.z,0.f), fmaxf(a.w,0.f)));
        __syncwarp();
        unsigned long long accp = *reinterpret_cast<const unsigned long long*>(sbsh + lane*2);
#pragma unroll 8
        for (int i = 0; i < 64; i++)
            ffma2(accp, *reinterpret_cast<const unsigned long long*>(&gd[warp][i]),
                  *reinterpret_cast<const unsigned long long*>(sWsh + i*64 + lane*2));
        float2 v = unpack2(accp);
        x1hu[nb + 96 + lane] = packh2(fmaxf(v.x,0.f), fmaxf(v.y,0.f));
        __syncwarp();
    }
}

// ---------------------------------------------------------------------------
// mma GEMM K=128: x1[:,0:128] = relu(h @ i2 + ib2). A=g_h fp16, B=g_i2t fp16.
// ---------------------------------------------------------------------------
#define MG128_SMEM 40960
__global__ void __launch_bounds__(256, 2) mma_gemm128(
    const __half* __restrict__ Ah, const __half* __restrict__ Bh,
    const float* __restrict__ bias, int N) {
    extern __shared__ char sm[];
    uint32_t smb = smem_u32(sm);
    int tid = threadIdx.x, lane = tid & 31, warp = tid >> 5;
    int wm = warp & 3, wn = warp >> 2;
    int rowBase = blockIdx.x * 128;
    float acc[2][8][4];
#pragma unroll
    for (int m = 0; m < 2; m++) for (int n = 0; n < 8; n++)
        for (int q = 0; q < 4; q++) acc[m][n][q] = 0.f;
    int aRow = lane & 15, aK = (lane >> 4) * 8;
    int bN = ((lane >> 4) << 3) + (lane & 7), bK = ((lane >> 3) & 1) * 8;
    int r0i = tid >> 2, q0 = (tid & 3);
    int r1i = (tid + 256) >> 2, q1 = ((tid + 256) & 3);

#define MG128_STAGE(kc, buf) do {                                                  \
    uint32_t bb = smb + (buf) * 20480;                                             \
    int rows[2] = {r0i, r1i}; int qs[2] = {q0, q1};                                \
    _Pragma("unroll")                                                              \
    for (int m = 0; m < 2; m++) {                                                  \
        int r = rows[m], q = qs[m];                                                \
        int row = rowBase + r; if (row > N-1) row = N-1;                           \
        uint32_t da = bb + r*80 + q*16;                                            \
        CP_ASYNC(da, Ah + (size_t)row*128 + (kc)*32 + q*8);                        \
        CP_ASYNC(da + 10240, Bh + (size_t)r*128 + (kc)*32 + q*8);                  \
    } } while (0)

    MG128_STAGE(0, 0);
    CP_COMMIT();
    for (int kc = 0; kc < 4; kc++) {
        int buf = kc & 1;
        if (kc < 3) { MG128_STAGE(kc + 1, buf ^ 1); CP_COMMIT(); CP_WAIT(1); }
        else CP_WAIT(0);
        __syncthreads();
        uint32_t bb = smb + buf * 20480;
#pragma unroll
        for (int ks = 0; ks < 32; ks += 16) {
            uint32_t ah[2][4], bh[4][4];
#pragma unroll
            for (int mt = 0; mt < 2; mt++)
                ldsm_x4(ah[mt], bb + ((wm*32 + mt*16 + aRow) * 40 + ks + aK) * 2);
#pragma unroll
            for (int bt = 0; bt < 4; bt++)
                ldsm_x4(bh[bt], bb + 10240 + ((wn*64 + bt*16 + bN) * 40 + ks + bK) * 2);
#pragma unroll
            for (int mt = 0; mt < 2; mt++)
#pragma unroll
                for (int nt = 0; nt < 8; nt++)
                    mma_f16(acc[mt][nt], ah[mt], &bh[nt>>1][(nt&1)*2]);
        }
        __syncthreads();
    }
    int g = lane >> 2, tq = (lane & 3) * 2;
    uint32_t* x1hu = reinterpret_cast<uint32_t*>(g_x1h);
#pragma unroll
    for (int mt = 0; mt < 2; mt++) {
        int r0 = rowBase + wm*32 + mt*16 + g;
#pragma unroll
        for (int nt = 0; nt < 8; nt++) {
            int c0 = wn*64 + nt*8 + tq;
            float b0 = __ldg(bias + c0), b1 = __ldg(bias + c0 + 1);
            if (r0 < N)
                x1hu[(size_t)r0*160 + (c0>>1)] =
                    packh2(fmaxf(acc[mt][nt][0]+b0,0.f), fmaxf(acc[mt][nt][1]+b1,0.f));
            if (r0 + 8 < N)
                x1hu[(size_t)(r0+8)*160 + (c0>>1)] =
                    packh2(fmaxf(acc[mt][nt][2]+b0,0.f), fmaxf(acc[mt][nt][3]+b1,0.f));
        }
    }
}

// ---------------------------------------------------------------------------
// mma GEMM K=320: hcn = x @ Wt^T + bc, output packed fp16.
// ---------------------------------------------------------------------------
#define MG_SMEM 40960
__global__ void __launch_bounds__(256, 2) mma_gemm(
    const __half* __restrict__ Ah, const __half* __restrict__ Bh,
    const float* __restrict__ bias, int N) {
    extern __shared__ char sm[];
    uint32_t smb = smem_u32(sm);
    int tid = threadIdx.x, lane = tid & 31, warp = tid >> 5;
    int wm = warp & 3, wn = warp >> 2;
    int rowBase = blockIdx.x * 128, colBase = blockIdx.y * 128;
    float acc[2][8][4];
#pragma unroll
    for (int m = 0; m < 2; m++) for (int n = 0; n < 8; n++)
        for (int q = 0; q < 4; q++) acc[m][n][q] = 0.f;
    int aRow = lane & 15, aK = (lane >> 4) * 8;
    int bN = ((lane >> 4) << 3) + (lane & 7), bK = ((lane >> 3) & 1) * 8;
    int r0i = tid >> 2, q0 = (tid & 3);
    int r1i = (tid + 256) >> 2, q1 = ((tid + 256) & 3);

#define MG_STAGE(kc, buf) do {                                                     \
    uint32_t bb = smb + (buf) * 20480;                                             \
    int rows[2] = {r0i, r1i}; int qs[2] = {q0, q1};                                \
    _Pragma("unroll")                                                              \
    for (int m = 0; m < 2; m++) {                                                  \
        int r = rows[m], q = qs[m];                                                \
        int row = rowBase + r; if (row > N-1) row = N-1;                           \
        uint32_t da = bb + r*80 + q*16;                                            \
        CP_ASYNC(da, Ah + (size_t)row*320 + (kc)*32 + q*8);                        \
        CP_ASYNC(da + 10240, Bh + (size_t)(colBase + r)*320 + (kc)*32 + q*8);      \
    } } while (0)

    MG_STAGE(0, 0);
    CP_COMMIT();
    for (int kc = 0; kc < 10; kc++) {
        int buf = kc & 1;
        if (kc < 9) { MG_STAGE(kc + 1, buf ^ 1); CP_COMMIT(); CP_WAIT(1); }
        else CP_WAIT(0);
        __syncthreads();
        uint32_t bb = smb + buf * 20480;
#pragma unroll
        for (int ks = 0; ks < 32; ks += 16) {
            uint32_t ah[2][4], bh[4][4];
#pragma unroll
            for (int mt = 0; mt < 2; mt++)
                ldsm_x4(ah[mt], bb + ((wm*32 + mt*16 + aRow) * 40 + ks + aK) * 2);
#pragma unroll
            for (int bt = 0; bt < 4; bt++)
                ldsm_x4(bh[bt], bb + 10240 + ((wn*64 + bt*16 + bN) * 40 + ks + bK) * 2);
#pragma unroll
            for (int mt = 0; mt < 2; mt++)
#pragma unroll
                for (int nt = 0; nt < 8; nt++)
                    mma_f16(acc[mt][nt], ah[mt], &bh[nt>>1][(nt&1)*2]);
        }
        __syncthreads();
    }
    int g = lane >> 2, tq = (lane & 3) * 2;
    uint32_t* hcu = reinterpret_cast<uint32_t*>(g_hcn);
#pragma unroll
    for (int mt = 0; mt < 2; mt++) {
        int r0 = rowBase + wm*32 + mt*16 + g;
#pragma unroll
        for (int nt = 0; nt < 8; nt++) {
            int c0 = colBase + wn*64 + nt*8 + tq;
            float b0 = __ldg(bias + c0), b1 = __ldg(bias + c0 + 1);
            if (r0 < N)
                hcu[(size_t)r0*128 + (c0>>1)] = packh2(acc[mt][nt][0]+b0, acc[mt][nt][1]+b1);
            if (r0 + 8 < N)
                hcu[(size_t)(r0+8)*128 + (c0>>1)] = packh2(acc[mt][nt][2]+b0, acc[mt][nt][3]+b1);
        }
    }
}

// ---------------------------------------------------------------------------
// Edge conv1 fp16: 384 threads, warps 0-7 mma (2/SMSP), 8-11 builders.
// smem: W2h @0 | R0 @34816 | R1 @69632 (each 34816B, pitch 136 halfs).
// ---------------------------------------------------------------------------
#define EP 136
#define E_SMEM 104448

__device__ __forceinline__ void edge1_build(char* sm, int roff, int tile,
                                            const int* __restrict__ src, int N, int tid2) {
    int r = tid2;
    int local = r & 31;
    int s = local / 10, j = local - s * 10;
    int n = tile * 12 + (r >> 5) * 3 + s;
    if (local < 30 && n < N) {
        int sidx = src[n + j * N];
        const uint4* hc4 = reinterpret_cast<const uint4*>(g_hcn + (size_t)n * 256);
        const uint4* hn4 = reinterpret_cast<const uint4*>(g_hcn + (size_t)sidx * 256 + 128);
        char* bh = sm + roff + r * (EP * 2);
        const __half2 z2 = __float2half2_rn(0.f);
#pragma unroll 4
        for (int i = 0; i < 16; i++) {
            uint4 a = hc4[i], b = hn4[i];
            const __half2* ap = reinterpret_cast<const __half2*>(&a);
            const __half2* bp = reinterpret_cast<const __half2*>(&b);
            uint4 o;
            __half2* op = reinterpret_cast<__half2*>(&o);
            op[0] = __hmax2(__hadd2(ap[0], bp[0]), z2);
            op[1] = __hmax2(__hadd2(ap[1], bp[1]), z2);
            op[2] = __hmax2(__hadd2(ap[2], bp[2]), z2);
            op[3] = __hmax2(__hadd2(ap[3], bp[3]), z2);
            *reinterpret_cast<uint4*>(bh + i * 16) = o;
        }
    }
    for (int q = tid2; q < 1152; q += 128) {
        int ln = q / 96, o = q - ln * 96, n2 = tile * 12 + ln;
        if (n2 < N) {
            size_t u = (size_t)n2 * 160 + 64 + o;
            reinterpret_cast<uint32_t*>(g_x2h)[u] = reinterpret_cast<const uint32_t*>(g_x1h)[u];
        }
    }
}

__global__ void __launch_bounds__(384, 1) edge1_mma(
    const int* __restrict__ src, const float* __restrict__ b2, int N, int ntiles) {
    extern __shared__ char sm[];
    __shared__ float b2s[128];
    int tid = threadIdx.x, lane = tid & 31, warp = tid >> 5;
    if (tid < 128) b2s[tid] = b2[tid];
    for (int idx = tid; idx < 2048; idx += 384) {
        int r = idx >> 4, kq = (idx & 15) * 8;
        *reinterpret_cast<uint4*>(sm + (r*EP + kq)*2) =
            *reinterpret_cast<const uint4*>(g_W2th + r*128 + kq);
    }
    for (int idx = tid; idx < 1088; idx += 384) {
        int rowsel = idx / 68, u = idx - rowsel * 68;
        int buf = rowsel >> 3, ri = rowsel & 7;
        int row = (ri >> 1) * 32 + 30 + (ri & 1);
        *reinterpret_cast<uint32_t*>(sm + 34816 + buf*34816 + row*(EP*2) + u*4) = 0u;
    }
    if (warp >= 8 && (int)blockIdx.x < ntiles)
        edge1_build(sm, 34816, blockIdx.x, src, N, tid - 256);
    __syncthreads();

    uint32_t smb = smem_u32(sm);
    uint32_t uW2h = smb;
    int aRow = lane & 15, aK = (lane >> 4) * 8;
    int bN_ = ((lane >> 4) << 3) + (lane & 7), bK = ((lane >> 3) & 1) * 8;
    int g = lane >> 2;
    int wm = warp & 3, wn = (warp >> 2) & 1;

    int lt = 0;
    for (int tile = blockIdx.x; tile < ntiles; tile += gridDim.x, lt ^= 1) {
        int roff = 34816 + lt * 34816;
        if (warp < 8) {
            uint32_t uR = smb + roff;
            float acc[2][8][4];
#pragma unroll
            for (int m = 0; m < 2; m++)
#pragma unroll
                for (int n = 0; n < 8; n++)
#pragma unroll
                    for (int q = 0; q < 4; q++) acc[m][n][q] = 0.f;
#pragma unroll
            for (int ks = 0; ks < 128; ks += 16) {
                uint32_t ah[2][4], bh[4][4];
#pragma unroll
                for (int mt = 0; mt < 2; mt++)
                    ldsm_x4(ah[mt], uR + ((wm*32 + mt*16 + aRow) * EP + ks + aK) * 2);
#pragma unroll
                for (int bt = 0; bt < 4; bt++)
                    ldsm_x4(bh[bt], uW2h + ((wn*64 + bt*16 + bN_) * EP + ks + bK) * 2);
#pragma unroll
                for (int mt = 0; mt < 2; mt++)
#pragma unroll
                    for (int nt = 0; nt < 8; nt++)
                        mma_f16(acc[mt][nt], ah[mt], &bh[nt>>1][(nt&1)*2]);
            }
            int n0 = tile * 12 + wm * 3;
#pragma unroll
            for (int nt = 0; nt < 8; nt++) {
                float e0 = acc[0][nt][0], o0 = acc[0][nt][1];
                if (g < 2) { e0 = fmaxf(e0, acc[0][nt][2]); o0 = fmaxf(o0, acc[0][nt][3]); }
                float e1 = (g >= 2) ? acc[0][nt][2] : -FLT_MAX;
                float o1 = (g >= 2) ? acc[0][nt][3] : -FLT_MAX;
                if (g < 4) { e1 = fmaxf(e1, acc[1][nt][0]); o1 = fmaxf(o1, acc[1][nt][1]); }
                float e2 = (g >= 4) ? acc[1][nt][0] : -FLT_MAX;
                float o2 = (g >= 4) ? acc[1][nt][1] : -FLT_MAX;
                if (g < 6) { e2 = fmaxf(e2, acc[1][nt][2]); o2 = fmaxf(o2, acc[1][nt][3]); }
#pragma unroll
                for (int off = 4; off <= 16; off <<= 1) {
                    e0 = fmaxf(e0, __shfl_xor_sync(0xffffffffu, e0, off));
                    o0 = fmaxf(o0, __shfl_xor_sync(0xffffffffu, o0, off));
                    e1 = fmaxf(e1, __shfl_xor_sync(0xffffffffu, e1, off));
                    o1 = fmaxf(o1, __shfl_xor_sync(0xffffffffu, o1, off));
                    e2 = fmaxf(e2, __shfl_xor_sync(0xffffffffu, e2, off));
                    o2 = fmaxf(o2, __shfl_xor_sync(0xffffffffu, o2, off));
                }
                if (lane < 4) {
                    int colb = wn*64 + nt*8 + lane*2;
                    float bce = b2s[colb], bco = b2s[colb+1];
                    float ve[3] = {fmaxf(e0+bce,0.f), fmaxf(e1+bce,0.f), fmaxf(e2+bce,0.f)};
                    float vo[3] = {fmaxf(o0+bco,0.f), fmaxf(o1+bco,0.f), fmaxf(o2+bco,0.f)};
#pragma unroll
                    for (int s = 0; s < 3; s++) {
                        int n = n0 + s;
                        if (n < N)
                            reinterpret_cast<uint32_t*>(g_x2h)[(size_t)n * 160 + (colb >> 1)] =
                                packh2(ve[s], vo[s]);
                    }
                }
            }
        } else {
            int nxt = tile + gridDim.x;
            if (nxt < ntiles)
                edge1_build(sm, 34816 + (lt ^ 1) * 34816, nxt, src, N, tid - 256);
        }
        __syncthreads();
    }
}

// ---------------------------------------------------------------------------
// Edge conv2 + scale: warp/node, fp16 hcn gathers, transpose-reduce.
// ---------------------------------------------------------------------------
__global__ void edge2_kernel(const int* __restrict__ src, const float* __restrict__ W2s,
                             const float* __restrict__ b2, float* __restrict__ out,
                             int N, int EPN) {
    int gw = (blockIdx.x * blockDim.x + threadIdx.x) >> 5;
    int lane = threadIdx.x & 31;
    if (gw >= N) return;
    int n = gw;
    int b0 = lane & 1, b1 = (lane >> 1) & 1;
    int c = 2*b0 + b1;
    float4 wr0 = *reinterpret_cast<const float4*>(W2s + (lane*4)*4);
    float4 wr1 = *reinterpret_cast<const float4*>(W2s + (lane*4+1)*4);
    float4 wr2 = *reinterpret_cast<const float4*>(W2s + (lane*4+2)*4);
    float4 wr3 = *reinterpret_cast<const float4*>(W2s + (lane*4+3)*4);
    float bc = __ldg(b2 + c);
    uint2 hcu = *reinterpret_cast<const uint2*>(g_hcn + (size_t)n*256 + lane*4);
    float2 hc0 = __half22float2(*reinterpret_cast<const __half2*>(&hcu.x));
    float2 hc1 = __half22float2(*reinterpret_cast<const __half2*>(&hcu.y));
    float mx = -FLT_MAX;
#pragma unroll
    for (int j = 0; j < 10; j++) {
        int s = src[n + j*N];
        uint2 hbu = *reinterpret_cast<const uint2*>(g_hcn + (size_t)s*256 + 128 + lane*4);
        float2 hb0 = __half22float2(*reinterpret_cast<const __half2*>(&hbu.x));
        float2 hb1 = __half22float2(*reinterpret_cast<const __half2*>(&hbu.y));
        float r0 = fmaxf(hc0.x+hb0.x,0.f), r1 = fmaxf(hc0.y+hb0.y,0.f);
        float r2 = fmaxf(hc1.x+hb1.x,0.f), r3 = fmaxf(hc1.y+hb1.y,0.f);
        float y0 = r0*wr0.x + r1*wr1.x + r2*wr2.x + r3*wr3.x;
        float y1 = r0*wr0.y + r1*wr1.y + r2*wr2.y + r3*wr3.y;
        float y2 = r0*wr0.z + r1*wr1.z + r2*wr2.z + r3*wr3.z;
        float y3 = r0*wr0.w + r1*wr1.w + r2*wr2.w + r3*wr3.w;
        float t0 = __shfl_xor_sync(0xffffffffu, b0 ? y0 : y2, 1);
        float t1 = __shfl_xor_sync(0xffffffffu, b0 ? y1 : y3, 1);
        float p0 = (b0 ? y2 : y0) + t0;
        float p1 = (b0 ? y3 : y1) + t1;
        float t2 = __shfl_xor_sync(0xffffffffu, b1 ? p0 : p1, 2);
        float z  = (b1 ? p1 : p0) + t2;
        z += __shfl_xor_sync(0xffffffffu, z, 4);
        z += __shfl_xor_sync(0xffffffffu, z, 8);
        z += __shfl_xor_sync(0xffffffffu, z, 16);
        mx = fmaxf(mx, z);
    }
    if (lane < 4) out[(size_t)n*4 + c] = (mx + bc) * g_sinv[n];
}

// ---------------------------------------------------------------------------
extern "C" void kernel_launch(void* const* d_in, const int* in_sizes, int n_in,
                              void* d_out, int out_size) {
    const float* t        = (const float*)d_in[0];
    const float* obj_x    = (const float*)d_in[1];
    const float* obj_geo  = (const float*)d_in[2];
    const float* wall     = (const float*)d_in[3];
    const int*   category = (const int*)d_in[4];
    const int*   batch_idx= (const int*)d_in[5];
    const int*   src      = (const int*)d_in[6];
    const float* embed_W  = (const float*)d_in[8];
    const float* gfp_W    = (const float*)d_in[9];
    const float* sW       = (const float*)d_in[10];
    const float* sb       = (const float*)d_in[11];
    const float* w1       = (const float*)d_in[12];
    const float* wb1      = (const float*)d_in[13];
    const float* w2       = (const float*)d_in[14];
    const float* wb2      = (const float*)d_in[15];
    const float* i1       = (const float*)d_in[16];
    const float* ib1      = (const float*)d_in[17];
    const float* i2       = (const float*)d_in[18];
    const float* ib2      = (const float*)d_in[19];
    const float* m1W1     = (const float*)d_in[20];
    const float* m1b1     = (const float*)d_in[21];
    const float* m1W2     = (const float*)d_in[22];
    const float* m1b2     = (const float*)d_in[23];
    const float* m2W1     = (const float*)d_in[24];
    const float* m2b1     = (const float*)d_in[25];
    const float* m2W2     = (const float*)d_in[26];
    const float* m2b2     = (const float*)d_in[27];

    int N = in_sizes[0], E = in_sizes[6], B = in_sizes[3] / 2;
    int EPN = E / N;
    int nt12 = (N + 11) / 12;

    float *p_bc1, *p_bc2;
    __half *p_h, *p_x1h, *p_x2h, *p_W1h, *p_W2h, *p_i2t;
    cudaGetSymbolAddress((void**)&p_h, g_h);
    cudaGetSymbolAddress((void**)&p_bc1, g_bc1);
    cudaGetSymbolAddress((void**)&p_bc2, g_bc2);
    cudaGetSymbolAddress((void**)&p_x1h, g_x1h);
    cudaGetSymbolAddress((void**)&p_x2h, g_x2h);
    cudaGetSymbolAddress((void**)&p_W1h, g_Wt1h);
    cudaGetSymbolAddress((void**)&p_W2h, g_Wt2h);
    cudaGetSymbolAddress((void**)&p_i2t, g_i2t);

    cudaFuncSetAttribute(mma_gemm, cudaFuncAttributeMaxDynamicSharedMemorySize, MG_SMEM);
    cudaFuncSetAttribute(mma_gemm128, cudaFuncAttributeMaxDynamicSharedMemorySize, MG128_SMEM);
    cudaFuncSetAttribute(edge1_mma, cudaFuncAttributeMaxDynamicSharedMemorySize, E_SMEM);

    setup_weights<<<768, 256>>>(m1W1, m1b1, m2W1, m2b1, m1W2, i2);
    setup_wall<<<(B + 3) / 4, 256>>>(wall, w1, wb1, w2, wb2, B);
    node_kernel<<<(N + 31) / 32, 256>>>(t, obj_x, obj_geo, category,
                                        batch_idx, embed_W, gfp_W, sW, sb, i1, ib1, N);
    mma_gemm128<<<(N + 127) / 128, 256, MG128_SMEM>>>(p_h, p_i2t, ib2, N);
    {
        dim3 g((N + 127) / 128, 2);
        mma_gemm<<<g, 256, MG_SMEM>>>(p_x1h, p_W1h, p_bc1, N);
    }
    edge1_mma<<<148, 384, E_SMEM>>>(src, m1b2, N, nt12);
    {
        dim3 g((N + 127) / 128, 2);
        mma_gemm<<<g, 256, MG_SMEM>>>(p_x2h, p_W2h, p_bc2, N);
    }
    edge2_kernel<<<(N + 7) / 8, 256>>>(src, m2W2, m2b2, (float*)d_out, N, EPN);
}

// round 17
// speedup vs baseline: 2.4534x; 1.1336x over previous
#include <cuda_runtime.h>
#include <cuda_fp16.h>
#include <math.h>
#include <float.h>
#include <stdint.h>

#define NMAX 50000
#define BMAX 1024

__device__ float g_wall_h[BMAX * 64];
__device__ __align__(16) __half g_hg[NMAX * 192];    // [h(128) | sin(32) | cos(32)]
__device__ __align__(16) __half g_hcn[NMAX * 256];   // fp16 [hc'(128) | hn(128)]
__device__ float g_sinv[NMAX];
__device__ __align__(16) __half g_x1h[NMAX * 320];
__device__ __align__(16) __half g_x2h[NMAX * 320];
__device__ __align__(16) __half g_Wt1h[256 * 320];
__device__ __align__(16) __half g_Wt2h[256 * 320];
__device__ __align__(16) __half g_W2th[128 * 128];
__device__ __align__(16) __half g_i2s[192 * 192];    // block-diag [i2 | sW] ^T
__device__ float g_bc1[256];
__device__ float g_bc2[256];

// ---- helpers ----
__device__ __forceinline__ uint32_t smem_u32(const void* p) {
    uint32_t a;
    asm("{ .reg .u64 t; cvta.to.shared.u64 t, %1; cvt.u32.u64 %0, t; }" : "=r"(a) : "l"(p));
    return a;
}
__device__ __forceinline__ void ldsm_x4(uint32_t* r, uint32_t addr) {
    asm volatile("ldmatrix.sync.aligned.m8n8.x4.shared.b16 {%0,%1,%2,%3}, [%4];"
                 : "=r"(r[0]), "=r"(r[1]), "=r"(r[2]), "=r"(r[3]) : "r"(addr));
}
__device__ __forceinline__ void mma_f16(float* c, const uint32_t* a, const uint32_t* b) {
    asm volatile("mma.sync.aligned.m16n8k16.row.col.f32.f16.f16.f32 "
                 "{%0,%1,%2,%3}, {%4,%5,%6,%7}, {%8,%9}, {%0,%1,%2,%3};"
                 : "+f"(c[0]), "+f"(c[1]), "+f"(c[2]), "+f"(c[3])
                 : "r"(a[0]), "r"(a[1]), "r"(a[2]), "r"(a[3]), "r"(b[0]), "r"(b[1]));
}
#define CP_ASYNC(dst, src) \
    asm volatile("cp.async.cg.shared.global [%0], [%1], 16;" :: "r"(dst), "l"(src) : "memory")
#define CP_COMMIT() asm volatile("cp.async.commit_group;" ::: "memory")
#define CP_WAIT(n)  asm volatile("cp.async.wait_group %0;" :: "n"(n) : "memory")

__device__ __forceinline__ uint32_t packh2(float a, float b) {
    __half2 p = __floats2half2_rn(a, b);
    return *reinterpret_cast<uint32_t*>(&p);
}

// ---------------------------------------------------------------------------
__global__ void __launch_bounds__(256) setup_weights(
    const float* __restrict__ m1W1, const float* __restrict__ m1b1,
    const float* __restrict__ m2W1, const float* __restrict__ m2b1,
    const float* __restrict__ m1W2, const float* __restrict__ i2,
    const float* __restrict__ sW) {
    int b = blockIdx.x, tid = threadIdx.x;
    if (b < 640) {
        int sel = b >= 320;
        const float* W1 = sel ? m2W1 : m1W1;
        const float* b1 = sel ? m2b1 : m1b1;
        __half* Wh = sel ? g_Wt2h : g_Wt1h;
        float* bc = sel ? g_bc2 : g_bc1;
        int idx = (sel ? b - 320 : b) * 256 + tid;
        if (idx < 256 * 320) {
            int c = idx / 320, k = idx - c * 320;
            float v = (c < 128) ? (W1[k*128+c] - W1[(k+320)*128+c]) : W1[(k+320)*128+(c-128)];
            Wh[idx] = __float2half_rn(v);
        }
        if (idx < 256) bc[idx] = (idx < 128) ? b1[idx] : 0.f;
    } else if (b < 704) {
        int idx = (b - 640) * 256 + tid;
        int c = idx >> 7, k = idx & 127;
        g_W2th[idx] = __float2half_rn(m1W2[k*128+c]);
    } else {
        int idx = (b - 704) * 256 + tid;
        if (idx < 192 * 192) {
            int c = idx / 192, k = idx - c * 192;
            float v = 0.f;
            if (c < 128) { if (k < 128) v = i2[k*128 + c]; }
            else         { if (k >= 128) v = sW[(k-128)*64 + (c-128)]; }
            g_i2s[idx] = __float2half_rn(v);
        }
    }
}

__global__ void __launch_bounds__(256) setup_wall(
    const float* __restrict__ wall, const float* __restrict__ w1,
    const float* __restrict__ wb1, const float* __restrict__ w2,
    const float* __restrict__ wb2, int B) {
    __shared__ float h[4][64];
    int tid = threadIdx.x;
    int row = blockIdx.x * 4 + (tid >> 6), k = tid & 63, rr = tid >> 6;
    if (row < B)
        h[rr][k] = fmaxf(wall[row*2]*w1[k] + wall[row*2+1]*w1[64+k] + wb1[k], 0.f);
    __syncthreads();
    if (row < B) {
        float acc = wb2[k];
#pragma unroll 8
        for (int i = 0; i < 64; i++) acc += h[rr][i] * w2[i*64+k];
        g_wall_h[row*64+k] = fmaxf(acc, 0.f);
    }
}

// ---------------------------------------------------------------------------
// Node: class/wall cond to x1, [h|sin|cos] to g_hg, sinv. FIXED gfp writer.
// ---------------------------------------------------------------------------
__global__ void __launch_bounds__(256) node_kernel(
    const float* __restrict__ t, const float* __restrict__ obj_x, const float* __restrict__ obj_geo,
    const int* __restrict__ category, const int* __restrict__ batch_idx,
    const float* __restrict__ embed_W, const float* __restrict__ gfp_W,
    const float* __restrict__ i1, const float* __restrict__ ib1, int N) {
    __shared__ float i1sh[6*128], embsh[10*64], gfpsh[32], ib1sh[128];
    int tid = threadIdx.x, warp = tid >> 5, lane = tid & 31;
    for (int i = tid; i < 768; i += 256) i1sh[i] = i1[i];
    for (int i = tid; i < 640; i += 256) embsh[i] = embed_W[i];
    if (tid < 32) gfpsh[tid] = gfp_W[tid];
    if (tid < 128) ib1sh[tid] = ib1[tid];
    __syncthreads();
    int base = blockIdx.x * 32;
#pragma unroll
    for (int it = 0; it < 4; it++) {
        int n = base + it * 8 + warp;
        if (n >= N) continue;
        float tv = __ldg(t + n);
        uint32_t* hgu = reinterpret_cast<uint32_t*>(g_hg);
        size_t hb = (size_t)n * 96;
        if (lane < 16) {   // 32 freqs: lane handles pair (2*lane, 2*lane+1)
            float p0 = tv * gfpsh[2*lane]   * 6.283185307179586f;
            float p1 = tv * gfpsh[2*lane+1] * 6.283185307179586f;
            hgu[hb + 64 + lane] = packh2(sinf(p0), sinf(p1));   // cols 128..159
            hgu[hb + 80 + lane] = packh2(cosf(p0), cosf(p1));   // cols 160..191
        }
        int cat = category[n], bi = batch_idx[n];
        uint32_t* x1hu = reinterpret_cast<uint32_t*>(g_x1h);
        size_t nb = (size_t)n * 160;
        x1hu[nb + 64 + lane] = packh2(fmaxf(embsh[cat*64 + 2*lane], 0.f),
                                      fmaxf(embsh[cat*64 + 2*lane + 1], 0.f));
        x1hu[nb + 128 + lane] = packh2(g_wall_h[bi*64 + 2*lane], g_wall_h[bi*64 + 2*lane + 1]);
        if (lane == 0) {
            const float LN25 = 3.2188758248682006f;
            float stdv = sqrtf((expf(2.f*tv*LN25) - 1.f) / (2.f*LN25));
            g_sinv[n] = 1.f / (stdv + 1e-7f);
        }
        float xv = 0.f;
        if (lane < 4) xv = obj_x[n*4+lane]; else if (lane < 6) xv = obj_geo[n*2+lane-4];
        float4 a = *reinterpret_cast<const float4*>(ib1sh + lane*4);
#pragma unroll
        for (int i = 0; i < 6; i++) {
            float xi = __shfl_sync(0xffffffffu, xv, i);
            float4 w = *reinterpret_cast<const float4*>(i1sh + i*128 + lane*4);
            a.x += xi*w.x; a.y += xi*w.y; a.z += xi*w.z; a.w += xi*w.w;
        }
        *reinterpret_cast<uint2*>(hgu + hb + lane*2) =
            make_uint2(packh2(fmaxf(a.x,0.f), fmaxf(a.y,0.f)),
                       packh2(fmaxf(a.z,0.f), fmaxf(a.w,0.f)));
    }
}

// ---------------------------------------------------------------------------
// Fused mma GEMM K=192: x1[0:128]=relu(h@i2+ib2), x1[192:256]=relu(gfp@sW+sb).
// ---------------------------------------------------------------------------
#define MG192_SMEM 51200
__global__ void __launch_bounds__(384, 1) mma_gemm192(
    const __half* __restrict__ Ah, const __half* __restrict__ Bh,
    const float* __restrict__ ib2, const float* __restrict__ sb, int N) {
    extern __shared__ char sm[];
    uint32_t smb = smem_u32(sm);
    int tid = threadIdx.x, lane = tid & 31, warp = tid >> 5;
    int wm = warp & 3, wn = warp >> 2;
    int rowBase = blockIdx.x * 128;
    float acc[2][8][4];
#pragma unroll
    for (int m = 0; m < 2; m++) for (int n = 0; n < 8; n++)
        for (int q = 0; q < 4; q++) acc[m][n][q] = 0.f;
    int aRow = lane & 15, aK = (lane >> 4) * 8;
    int bN = ((lane >> 4) << 3) + (lane & 7), bK = ((lane >> 3) & 1) * 8;

#define MG192_STAGE(kc, buf) do {                                                  \
    uint32_t bb = smb + (buf) * 25600;                                             \
    for (int idx = tid; idx < 1280; idx += 384) {                                  \
        int r = idx >> 2, q = idx & 3;                                             \
        uint32_t da = bb + r*80 + q*16;                                            \
        if (r < 128) {                                                             \
            int row = rowBase + r; if (row > N-1) row = N-1;                       \
            CP_ASYNC(da, Ah + (size_t)row*192 + (kc)*32 + q*8);                    \
        } else {                                                                   \
            CP_ASYNC(da, Bh + (size_t)(r-128)*192 + (kc)*32 + q*8);                \
        }                                                                          \
    } } while (0)

    MG192_STAGE(0, 0);
    CP_COMMIT();
    for (int kc = 0; kc < 6; kc++) {
        int buf = kc & 1;
        if (kc < 5) { MG192_STAGE(kc + 1, buf ^ 1); CP_COMMIT(); CP_WAIT(1); }
        else CP_WAIT(0);
        __syncthreads();
        uint32_t bb = smb + buf * 25600;
#pragma unroll
        for (int ks = 0; ks < 32; ks += 16) {
            uint32_t ah[2][4], bh[4][4];
#pragma unroll
            for (int mt = 0; mt < 2; mt++)
                ldsm_x4(ah[mt], bb + ((wm*32 + mt*16 + aRow) * 40 + ks + aK) * 2);
#pragma unroll
            for (int bt = 0; bt < 4; bt++)
                ldsm_x4(bh[bt], bb + 10240 + ((wn*64 + bt*16 + bN) * 40 + ks + bK) * 2);
#pragma unroll
            for (int mt = 0; mt < 2; mt++)
#pragma unroll
                for (int nt = 0; nt < 8; nt++)
                    mma_f16(acc[mt][nt], ah[mt], &bh[nt>>1][(nt&1)*2]);
        }
        __syncthreads();
    }
    int g = lane >> 2, tq = (lane & 3) * 2;
    uint32_t* x1hu = reinterpret_cast<uint32_t*>(g_x1h);
#pragma unroll
    for (int mt = 0; mt < 2; mt++) {
        int r0 = rowBase + wm*32 + mt*16 + g;
#pragma unroll
        for (int nt = 0; nt < 8; nt++) {
            int c0 = wn*64 + nt*8 + tq;
            float b0, b1;
            int xcol;
            if (c0 < 128) { b0 = __ldg(ib2 + c0); b1 = __ldg(ib2 + c0 + 1); xcol = c0; }
            else          { b0 = __ldg(sb + c0 - 128); b1 = __ldg(sb + c0 - 127); xcol = c0 + 64; }
            if (r0 < N)
                x1hu[(size_t)r0*160 + (xcol>>1)] =
                    packh2(fmaxf(acc[mt][nt][0]+b0,0.f), fmaxf(acc[mt][nt][1]+b1,0.f));
            if (r0 + 8 < N)
                x1hu[(size_t)(r0+8)*160 + (xcol>>1)] =
                    packh2(fmaxf(acc[mt][nt][2]+b0,0.f), fmaxf(acc[mt][nt][3]+b1,0.f));
        }
    }
}

// ---------------------------------------------------------------------------
// mma GEMM K=320: hcn = x @ Wt^T + bc, output packed fp16.
// ---------------------------------------------------------------------------
#define MG_SMEM 40960
__global__ void __launch_bounds__(256, 2) mma_gemm(
    const __half* __restrict__ Ah, const __half* __restrict__ Bh,
    const float* __restrict__ bias, int N) {
    extern __shared__ char sm[];
    uint32_t smb = smem_u32(sm);
    int tid = threadIdx.x, lane = tid & 31, warp = tid >> 5;
    int wm = warp & 3, wn = warp >> 2;
    int rowBase = blockIdx.x * 128, colBase = blockIdx.y * 128;
    float acc[2][8][4];
#pragma unroll
    for (int m = 0; m < 2; m++) for (int n = 0; n < 8; n++)
        for (int q = 0; q < 4; q++) acc[m][n][q] = 0.f;
    int aRow = lane & 15, aK = (lane >> 4) * 8;
    int bN = ((lane >> 4) << 3) + (lane & 7), bK = ((lane >> 3) & 1) * 8;
    int r0i = tid >> 2, q0 = (tid & 3);
    int r1i = (tid + 256) >> 2, q1 = ((tid + 256) & 3);

#define MG_STAGE(kc, buf) do {                                                     \
    uint32_t bb = smb + (buf) * 20480;                                             \
    int rows[2] = {r0i, r1i}; int qs[2] = {q0, q1};                                \
    _Pragma("unroll")                                                              \
    for (int m = 0; m < 2; m++) {                                                  \
        int r = rows[m], q = qs[m];                                                \
        int row = rowBase + r; if (row > N-1) row = N-1;                           \
        uint32_t da = bb + r*80 + q*16;                                            \
        CP_ASYNC(da, Ah + (size_t)row*320 + (kc)*32 + q*8);                        \
        CP_ASYNC(da + 10240, Bh + (size_t)(colBase + r)*320 + (kc)*32 + q*8);      \
    } } while (0)

    MG_STAGE(0, 0);
    CP_COMMIT();
    for (int kc = 0; kc < 10; kc++) {
        int buf = kc & 1;
        if (kc < 9) { MG_STAGE(kc + 1, buf ^ 1); CP_COMMIT(); CP_WAIT(1); }
        else CP_WAIT(0);
        __syncthreads();
        uint32_t bb = smb + buf * 20480;
#pragma unroll
        for (int ks = 0; ks < 32; ks += 16) {
            uint32_t ah[2][4], bh[4][4];
#pragma unroll
            for (int mt = 0; mt < 2; mt++)
                ldsm_x4(ah[mt], bb + ((wm*32 + mt*16 + aRow) * 40 + ks + aK) * 2);
#pragma unroll
            for (int bt = 0; bt < 4; bt++)
                ldsm_x4(bh[bt], bb + 10240 + ((wn*64 + bt*16 + bN) * 40 + ks + bK) * 2);
#pragma unroll
            for (int mt = 0; mt < 2; mt++)
#pragma unroll
                for (int nt = 0; nt < 8; nt++)
                    mma_f16(acc[mt][nt], ah[mt], &bh[nt>>1][(nt&1)*2]);
        }
        __syncthreads();
    }
    int g = lane >> 2, tq = (lane & 3) * 2;
    uint32_t* hcu = reinterpret_cast<uint32_t*>(g_hcn);
#pragma unroll
    for (int mt = 0; mt < 2; mt++) {
        int r0 = rowBase + wm*32 + mt*16 + g;
#pragma unroll
        for (int nt = 0; nt < 8; nt++) {
            int c0 = colBase + wn*64 + nt*8 + tq;
            float b0 = __ldg(bias + c0), b1 = __ldg(bias + c0 + 1);
            if (r0 < N)
                hcu[(size_t)r0*128 + (c0>>1)] = packh2(acc[mt][nt][0]+b0, acc[mt][nt][1]+b1);
            if (r0 + 8 < N)
                hcu[(size_t)(r0+8)*128 + (c0>>1)] = packh2(acc[mt][nt][2]+b0, acc[mt][nt][3]+b1);
        }
    }
}

// ---------------------------------------------------------------------------
// Edge conv1 fp16: 384 threads, warps 0-7 mma, 8-11 builders (chunk de-dup).
// smem: W2h @0 | R0 @34816 | R1 @69632 (each 34816B, pitch 136 halfs).
// ---------------------------------------------------------------------------
#define EP 136
#define E_SMEM 104448

__device__ __forceinline__ void edge1_build(char* sm, int roff, int tile,
                                            const int* __restrict__ src, int N, int tid2) {
    if (tid2 < 96) {
        int ln = tid2 >> 3, q = tid2 & 7;
        int n = tile * 12 + ln;
        if (n < N) {
            int rowb = (ln / 3) * 32 + (ln % 3) * 10;
            const uint4* hc4 = reinterpret_cast<const uint4*>(g_hcn + (size_t)n*256 + q*16);
            uint4 a0 = hc4[0], a1 = hc4[1];
            const __half2* ap0 = reinterpret_cast<const __half2*>(&a0);
            const __half2* ap1 = reinterpret_cast<const __half2*>(&a1);
            const __half2 z2 = __float2half2_rn(0.f);
            int sidx[10];
#pragma unroll
            for (int j = 0; j < 10; j++) sidx[j] = src[n + j*N];
#pragma unroll
            for (int j = 0; j < 10; j++) {
                const uint4* hn4 = reinterpret_cast<const uint4*>(
                    g_hcn + (size_t)sidx[j]*256 + 128 + q*16);
                uint4 b0 = hn4[0], b1 = hn4[1];
                const __half2* bp0 = reinterpret_cast<const __half2*>(&b0);
                const __half2* bp1 = reinterpret_cast<const __half2*>(&b1);
                uint4 o0, o1;
                __half2* op0 = reinterpret_cast<__half2*>(&o0);
                __half2* op1 = reinterpret_cast<__half2*>(&o1);
#pragma unroll
                for (int v = 0; v < 4; v++) {
                    op0[v] = __hmax2(__hadd2(ap0[v], bp0[v]), z2);
                    op1[v] = __hmax2(__hadd2(ap1[v], bp1[v]), z2);
                }
                char* dst = sm + roff + ((rowb + j)*EP + q*16)*2;
                *reinterpret_cast<uint4*>(dst) = o0;
                *reinterpret_cast<uint4*>(dst + 16) = o1;
            }
        }
    }
    for (int qq = tid2; qq < 1152; qq += 128) {
        int ln = qq / 96, o = qq - ln * 96, n2 = tile * 12 + ln;
        if (n2 < N) {
            size_t u = (size_t)n2 * 160 + 64 + o;
            reinterpret_cast<uint32_t*>(g_x2h)[u] = reinterpret_cast<const uint32_t*>(g_x1h)[u];
        }
    }
}

__global__ void __launch_bounds__(384, 1) edge1_mma(
    const int* __restrict__ src, const float* __restrict__ b2, int N, int ntiles) {
    extern __shared__ char sm[];
    __shared__ float b2s[128];
    int tid = threadIdx.x, lane = tid & 31, warp = tid >> 5;
    if (tid < 128) b2s[tid] = b2[tid];
    for (int idx = tid; idx < 2048; idx += 384) {
        int r = idx >> 4, kq = (idx & 15) * 8;
        *reinterpret_cast<uint4*>(sm + (r*EP + kq)*2) =
            *reinterpret_cast<const uint4*>(g_W2th + r*128 + kq);
    }
    for (int idx = tid; idx < 1088; idx += 384) {
        int rowsel = idx / 68, u = idx - rowsel * 68;
        int buf = rowsel >> 3, ri = rowsel & 7;
        int row = (ri >> 1) * 32 + 30 + (ri & 1);
        *reinterpret_cast<uint32_t*>(sm + 34816 + buf*34816 + row*(EP*2) + u*4) = 0u;
    }
    if (warp >= 8 && (int)blockIdx.x < ntiles)
        edge1_build(sm, 34816, blockIdx.x, src, N, tid - 256);
    __syncthreads();

    uint32_t smb = smem_u32(sm);
    uint32_t uW2h = smb;
    int aRow = lane & 15, aK = (lane >> 4) * 8;
    int bN_ = ((lane >> 4) << 3) + (lane & 7), bK = ((lane >> 3) & 1) * 8;
    int g = lane >> 2;
    int wm = warp & 3, wn = (warp >> 2) & 1;

    int lt = 0;
    for (int tile = blockIdx.x; tile < ntiles; tile += gridDim.x, lt ^= 1) {
        int roff = 34816 + lt * 34816;
        if (warp < 8) {
            uint32_t uR = smb + roff;
            float acc[2][8][4];
#pragma unroll
            for (int m = 0; m < 2; m++)
#pragma unroll
                for (int n = 0; n < 8; n++)
#pragma unroll
                    for (int q = 0; q < 4; q++) acc[m][n][q] = 0.f;
#pragma unroll
            for (int ks = 0; ks < 128; ks += 16) {
                uint32_t ah[2][4], bh[4][4];
#pragma unroll
                for (int mt = 0; mt < 2; mt++)
                    ldsm_x4(ah[mt], uR + ((wm*32 + mt*16 + aRow) * EP + ks + aK) * 2);
#pragma unroll
                for (int bt = 0; bt < 4; bt++)
                    ldsm_x4(bh[bt], uW2h + ((wn*64 + bt*16 + bN_) * EP + ks + bK) * 2);
#pragma unroll
                for (int mt = 0; mt < 2; mt++)
#pragma unroll
                    for (int nt = 0; nt < 8; nt++)
                        mma_f16(acc[mt][nt], ah[mt], &bh[nt>>1][(nt&1)*2]);
            }
            int n0 = tile * 12 + wm * 3;
#pragma unroll
            for (int nt = 0; nt < 8; nt++) {
                float e0 = acc[0][nt][0], o0 = acc[0][nt][1];
                if (g < 2) { e0 = fmaxf(e0, acc[0][nt][2]); o0 = fmaxf(o0, acc[0][nt][3]); }
                float e1 = (g >= 2) ? acc[0][nt][2] : -FLT_MAX;
                float o1 = (g >= 2) ? acc[0][nt][3] : -FLT_MAX;
                if (g < 4) { e1 = fmaxf(e1, acc[1][nt][0]); o1 = fmaxf(o1, acc[1][nt][1]); }
                float e2 = (g >= 4) ? acc[1][nt][0] : -FLT_MAX;
                float o2 = (g >= 4) ? acc[1][nt][1] : -FLT_MAX;
                if (g < 6) { e2 = fmaxf(e2, acc[1][nt][2]); o2 = fmaxf(o2, acc[1][nt][3]); }
#pragma unroll
                for (int off = 4; off <= 16; off <<= 1) {
                    e0 = fmaxf(e0, __shfl_xor_sync(0xffffffffu, e0, off));
                    o0 = fmaxf(o0, __shfl_xor_sync(0xffffffffu, o0, off));
                    e1 = fmaxf(e1, __shfl_xor_sync(0xffffffffu, e1, off));
                    o1 = fmaxf(o1, __shfl_xor_sync(0xffffffffu, o1, off));
                    e2 = fmaxf(e2, __shfl_xor_sync(0xffffffffu, e2, off));
                    o2 = fmaxf(o2, __shfl_xor_sync(0xffffffffu, o2, off));
                }
                if (lane < 4) {
                    int colb = wn*64 + nt*8 + lane*2;
                    float bce = b2s[colb], bco = b2s[colb+1];
                    float ve[3] = {fmaxf(e0+bce,0.f), fmaxf(e1+bce,0.f), fmaxf(e2+bce,0.f)};
                    float vo[3] = {fmaxf(o0+bco,0.f), fmaxf(o1+bco,0.f), fmaxf(o2+bco,0.f)};
#pragma unroll
                    for (int s = 0; s < 3; s++) {
                        int n = n0 + s;
                        if (n < N)
                            reinterpret_cast<uint32_t*>(g_x2h)[(size_t)n * 160 + (colb >> 1)] =
                                packh2(ve[s], vo[s]);
                    }
                }
            }
        } else {
            int nxt = tile + gridDim.x;
            if (nxt < ntiles)
                edge1_build(sm, 34816 + (lt ^ 1) * 34816, nxt, src, N, tid - 256);
        }
        __syncthreads();
    }
}

// ---------------------------------------------------------------------------
__global__ void edge2_kernel(const int* __restrict__ src, const float* __restrict__ W2s,
                             const float* __restrict__ b2, float* __restrict__ out,
                             int N, int EPN) {
    int gw = (blockIdx.x * blockDim.x + threadIdx.x) >> 5;
    int lane = threadIdx.x & 31;
    if (gw >= N) return;
    int n = gw;
    int b0 = lane & 1, b1 = (lane >> 1) & 1;
    int c = 2*b0 + b1;
    float4 wr0 = *reinterpret_cast<const float4*>(W2s + (lane*4)*4);
    float4 wr1 = *reinterpret_cast<const float4*>(W2s + (lane*4+1)*4);
    float4 wr2 = *reinterpret_cast<const float4*>(W2s + (lane*4+2)*4);
    float4 wr3 = *reinterpret_cast<const float4*>(W2s + (lane*4+3)*4);
    float bc = __ldg(b2 + c);
    uint2 hcu = *reinterpret_cast<const uint2*>(g_hcn + (size_t)n*256 + lane*4);
    float2 hc0 = __half22float2(*reinterpret_cast<const __half2*>(&hcu.x));
    float2 hc1 = __half22float2(*reinterpret_cast<const __half2*>(&hcu.y));
    float mx = -FLT_MAX;
#pragma unroll
    for (int j = 0; j < 10; j++) {
        int s = src[n + j*N];
        uint2 hbu = *reinterpret_cast<const uint2*>(g_hcn + (size_t)s*256 + 128 + lane*4);
        float2 hb0 = __half22float2(*reinterpret_cast<const __half2*>(&hbu.x));
        float2 hb1 = __half22float2(*reinterpret_cast<const __half2*>(&hbu.y));
        float r0 = fmaxf(hc0.x+hb0.x,0.f), r1 = fmaxf(hc0.y+hb0.y,0.f);
        float r2 = fmaxf(hc1.x+hb1.x,0.f), r3 = fmaxf(hc1.y+hb1.y,0.f);
        float y0 = r0*wr0.x + r1*wr1.x + r2*wr2.x + r3*wr3.x;
        float y1 = r0*wr0.y + r1*wr1.y + r2*wr2.y + r3*wr3.y;
        float y2 = r0*wr0.z + r1*wr1.z + r2*wr2.z + r3*wr3.z;
        float y3 = r0*wr0.w + r1*wr1.w + r2*wr2.w + r3*wr3.w;
        float t0 = __shfl_xor_sync(0xffffffffu, b0 ? y0 : y2, 1);
        float t1 = __shfl_xor_sync(0xffffffffu, b0 ? y1 : y3, 1);
        float p0 = (b0 ? y2 : y0) + t0;
        float p1 = (b0 ? y3 : y1) + t1;
        float t2 = __shfl_xor_sync(0xffffffffu, b1 ? p0 : p1, 2);
        float z  = (b1 ? p1 : p0) + t2;
        z += __shfl_xor_sync(0xffffffffu, z, 4);
        z += __shfl_xor_sync(0xffffffffu, z, 8);
        z += __shfl_xor_sync(0xffffffffu, z, 16);
        mx = fmaxf(mx, z);
    }
    if (lane < 4) out[(size_t)n*4 + c] = (mx + bc) * g_sinv[n];
}

// ---------------------------------------------------------------------------
extern "C" void kernel_launch(void* const* d_in, const int* in_sizes, int n_in,
                              void* d_out, int out_size) {
    const float* t        = (const float*)d_in[0];
    const float* obj_x    = (const float*)d_in[1];
    const float* obj_geo  = (const float*)d_in[2];
    const float* wall     = (const float*)d_in[3];
    const int*   category = (const int*)d_in[4];
    const int*   batch_idx= (const int*)d_in[5];
    const int*   src      = (const int*)d_in[6];
    const float* embed_W  = (const float*)d_in[8];
    const float* gfp_W    = (const float*)d_in[9];
    const float* sW       = (const float*)d_in[10];
    const float* sb       = (const float*)d_in[11];
    const float* w1       = (const float*)d_in[12];
    const float* wb1      = (const float*)d_in[13];
    const float* w2       = (const float*)d_in[14];
    const float* wb2      = (const float*)d_in[15];
    const float* i1       = (const float*)d_in[16];
    const float* ib1      = (const float*)d_in[17];
    const float* i2       = (const float*)d_in[18];
    const float* ib2      = (const float*)d_in[19];
    const float* m1W1     = (const float*)d_in[20];
    const float* m1b1     = (const float*)d_in[21];
    const float* m1W2     = (const float*)d_in[22];
    const float* m1b2     = (const float*)d_in[23];
    const float* m2W1     = (const float*)d_in[24];
    const float* m2b1     = (const float*)d_in[25];
    const float* m2W2     = (const float*)d_in[26];
    const float* m2b2     = (const float*)d_in[27];

    int N = in_sizes[0], E = in_sizes[6], B = in_sizes[3] / 2;
    int EPN = E / N;
    int nt12 = (N + 11) / 12;

    float *p_bc1, *p_bc2;
    __half *p_hg, *p_x1h, *p_x2h, *p_W1h, *p_W2h, *p_i2s;
    cudaGetSymbolAddress((void**)&p_hg, g_hg);
    cudaGetSymbolAddress((void**)&p_bc1, g_bc1);
    cudaGetSymbolAddress((void**)&p_bc2, g_bc2);
    cudaGetSymbolAddress((void**)&p_x1h, g_x1h);
    cudaGetSymbolAddress((void**)&p_x2h, g_x2h);
    cudaGetSymbolAddress((void**)&p_W1h, g_Wt1h);
    cudaGetSymbolAddress((void**)&p_W2h, g_Wt2h);
    cudaGetSymbolAddress((void**)&p_i2s, g_i2s);

    cudaFuncSetAttribute(mma_gemm, cudaFuncAttributeMaxDynamicSharedMemorySize, MG_SMEM);
    cudaFuncSetAttribute(mma_gemm192, cudaFuncAttributeMaxDynamicSharedMemorySize, MG192_SMEM);
    cudaFuncSetAttribute(edge1_mma, cudaFuncAttributeMaxDynamicSharedMemorySize, E_SMEM);

    setup_weights<<<848, 256>>>(m1W1, m1b1, m2W1, m2b1, m1W2, i2, sW);
    setup_wall<<<(B + 3) / 4, 256>>>(wall, w1, wb1, w2, wb2, B);
    node_kernel<<<(N + 31) / 32, 256>>>(t, obj_x, obj_geo, category,
                                        batch_idx, embed_W, gfp_W, i1, ib1, N);
    mma_gemm192<<<(N + 127) / 128, 384, MG192_SMEM>>>(p_hg, p_i2s, ib2, sb, N);
    {
        dim3 g((N + 127) / 128, 2);
        mma_gemm<<<g, 256, MG_SMEM>>>(p_x1h, p_W1h, p_bc1, N);
    }
    edge1_mma<<<148, 384, E_SMEM>>>(src, m1b2, N, nt12);
    {
        dim3 g((N + 127) / 128, 2);
        mma_gemm<<<g, 256, MG_SMEM>>>(p_x2h, p_W2h, p_bc2, N);
    }
    edge2_kernel<<<(N + 7) / 8, 256>>>(src, m2W2, m2b2, (float*)d_out, N, EPN);
}